// round 13
// baseline (speedup 1.0000x reference)
#include <cuda_runtime.h>
#include <cuda_bf16.h>
#include <cstdint>
#include <math.h>

#define Tt 2048
#define Dd 1024
#define Hh 16
#define D3 3072
#define NT 4096      // B*T
#define BHn 32       // B*H

typedef __nv_bfloat16 bf16;

// ---------------- scratch ----------------
__device__ bf16 g_qkv_hi[(size_t)NT * D3];
__device__ bf16 g_qkv_lo[(size_t)NT * D3];
__device__ bf16 g_x_hi[(size_t)NT * Dd];
__device__ bf16 g_x_lo[(size_t)NT * Dd];
__device__ bf16 g_att_hi[(size_t)NT * Dd];
__device__ bf16 g_att_lo[(size_t)NT * Dd];
__device__ bf16 g_wt_hi[(size_t)D3 * Dd];
__device__ bf16 g_wt_lo[(size_t)D3 * Dd];
__device__ bf16 g_wot_hi[(size_t)Dd * Dd];
__device__ bf16 g_wot_lo[(size_t)Dd * Dd];
__device__ bf16 g_vt_hi[(size_t)BHn * 64 * Tt];
__device__ bf16 g_vt_lo[(size_t)BHn * 64 * Tt];
__device__ float g_l[(size_t)BHn * Tt];     // row sums (unnormalized)

// ---------------- helpers ----------------
__device__ __forceinline__ uint32_t smem_u32(const void* p) {
    uint32_t a;
    asm("{ .reg .u64 t; cvta.to.shared.u64 t, %1; cvt.u32.u64 %0, t; }" : "=r"(a) : "l"(p));
    return a;
}

#define LDSM_X4(r0, r1, r2, r3, a) \
    asm volatile("ldmatrix.sync.aligned.m8n8.x4.shared.b16 {%0,%1,%2,%3}, [%4];" \
                 : "=r"(r0), "=r"(r1), "=r"(r2), "=r"(r3) : "r"(a))

#define MMA16816(c, a, b) \
    asm volatile("mma.sync.aligned.m16n8k16.row.col.f32.bf16.bf16.f32 " \
                 "{%0,%1,%2,%3}, {%4,%5,%6,%7}, {%8,%9}, {%0,%1,%2,%3};" \
                 : "+f"((c)[0]), "+f"((c)[1]), "+f"((c)[2]), "+f"((c)[3]) \
                 : "r"((a)[0]), "r"((a)[1]), "r"((a)[2]), "r"((a)[3]), \
                   "r"((b)[0]), "r"((b)[1]))

#define CP16(dst, src) \
    asm volatile("cp.async.cg.shared.global [%0], [%1], 16;" :: "r"(dst), "l"(src) : "memory")
#define CPCOMMIT() asm volatile("cp.async.commit_group;" ::: "memory")
#define CPWAIT2()  asm volatile("cp.async.wait_group 2;" ::: "memory")
#define CPWAIT1()  asm volatile("cp.async.wait_group 1;" ::: "memory")
#define CPWAIT0()  asm volatile("cp.async.wait_group 0;" ::: "memory")

__device__ __forceinline__ uint64_t pack4(bf16 a, bf16 b, bf16 c, bf16 d) {
    __nv_bfloat162 p0(a, b), p1(c, d);
    uint32_t u0 = *(uint32_t*)&p0, u1 = *(uint32_t*)&p1;
    return ((uint64_t)u1 << 32) | u0;
}

__device__ __forceinline__ void st_split2(bf16* __restrict__ H, bf16* __restrict__ L,
                                          size_t off, float a, float b) {
    bf16 ha = __float2bfloat16(a), hb = __float2bfloat16(b);
    *(__nv_bfloat162*)(H + off) = __nv_bfloat162(ha, hb);
    *(__nv_bfloat162*)(L + off) =
        __nv_bfloat162(__float2bfloat16(a - __bfloat162float(ha)),
                       __float2bfloat16(b - __bfloat162float(hb)));
}

// split a float pair into packed bf16 hi + lo u32 regs
__device__ __forceinline__ void split2r(float a, float b, uint32_t& h, uint32_t& l) {
    bf16 ha = __float2bfloat16(a), hb = __float2bfloat16(b);
    __nv_bfloat162 H(ha, hb);
    h = *(uint32_t*)&H;
    __nv_bfloat162 L(__float2bfloat16(a - __bfloat162float(ha)),
                     __float2bfloat16(b - __bfloat162float(hb)));
    l = *(uint32_t*)&L;
}

// async-copy a rows x 64 bf16 tile into padded smem (144B rows)
__device__ __forceinline__ void cpa_tile(uint32_t s_dst, const bf16* __restrict__ src,
                                         int stride, int rows) {
    for (int e = threadIdx.x; e < rows * 8; e += 256) {
        int r = e >> 3, c = e & 7;
        CP16(s_dst + (uint32_t)(r * 144 + c * 16), src + (size_t)r * stride + c * 8);
    }
}

// async-copy a 128 x 32 bf16 tile into padded smem (80B rows)
__device__ __forceinline__ void cpa_tile32(uint32_t s_dst, const bf16* __restrict__ src,
                                           int stride) {
    for (int e = threadIdx.x; e < 128 * 4; e += 256) {
        int r = e >> 2, c = e & 3;
        CP16(s_dst + (uint32_t)(r * 80 + c * 16), src + (size_t)r * stride + c * 8);
    }
}

// generic pass; RS = smem row stride bytes
template<int MI, int NI, int NKB, int RS>
__device__ __forceinline__ void mma_pass(float (*acc)[NI][4], uint32_t sA, uint32_t sB,
                                         int lane, int m0, int n0) {
    #pragma unroll
    for (int kb = 0; kb < NKB; kb++) {
        uint32_t a[MI][4];
        #pragma unroll
        for (int mi = 0; mi < MI; mi++) {
            uint32_t ad = sA + (uint32_t)((m0 + mi * 16 + (lane & 15)) * RS
                                          + kb * 32 + ((lane >> 4) << 4));
            LDSM_X4(a[mi][0], a[mi][1], a[mi][2], a[mi][3], ad);
        }
        uint32_t b[NI][2];
        #pragma unroll
        for (int nb = 0; nb < NI / 2; nb++) {
            uint32_t ad = sB + (uint32_t)((n0 + nb * 16 + ((lane >> 4) << 3) + (lane & 7)) * RS
                                          + kb * 32 + (((lane >> 3) & 1) << 4));
            uint32_t r0, r1, r2, r3;
            LDSM_X4(r0, r1, r2, r3, ad);
            b[2 * nb][0] = r0; b[2 * nb][1] = r1;
            b[2 * nb + 1][0] = r2; b[2 * nb + 1][1] = r3;
        }
        #pragma unroll
        for (int mi = 0; mi < MI; mi++)
            #pragma unroll
            for (int ni = 0; ni < NI; ni++)
                MMA16816(acc[mi][ni], a[mi], b[ni]);
    }
}

// fused hi/lo pass: load Ah/Al/Bh/Bl fragments once, 3 MMAs per (mi,ni)
template<int MI, int NI, int NKB, int RS>
__device__ __forceinline__ void mma_pass3(float (*acc)[NI][4],
                                          uint32_t sAh, uint32_t sAl,
                                          uint32_t sBh, uint32_t sBl,
                                          int lane, int m0, int n0) {
    #pragma unroll
    for (int kb = 0; kb < NKB; kb++) {
        uint32_t ah[MI][4], al[MI][4];
        #pragma unroll
        for (int mi = 0; mi < MI; mi++) {
            uint32_t off = (uint32_t)((m0 + mi * 16 + (lane & 15)) * RS
                                      + kb * 32 + ((lane >> 4) << 4));
            LDSM_X4(ah[mi][0], ah[mi][1], ah[mi][2], ah[mi][3], sAh + off);
            LDSM_X4(al[mi][0], al[mi][1], al[mi][2], al[mi][3], sAl + off);
        }
        uint32_t bh[NI][2], bl[NI][2];
        #pragma unroll
        for (int nb = 0; nb < NI / 2; nb++) {
            uint32_t off = (uint32_t)((n0 + nb * 16 + ((lane >> 4) << 3) + (lane & 7)) * RS
                                      + kb * 32 + (((lane >> 3) & 1) << 4));
            uint32_t r0, r1, r2, r3;
            LDSM_X4(r0, r1, r2, r3, sBh + off);
            bh[2 * nb][0] = r0; bh[2 * nb][1] = r1;
            bh[2 * nb + 1][0] = r2; bh[2 * nb + 1][1] = r3;
            LDSM_X4(r0, r1, r2, r3, sBl + off);
            bl[2 * nb][0] = r0; bl[2 * nb][1] = r1;
            bl[2 * nb + 1][0] = r2; bl[2 * nb + 1][1] = r3;
        }
        #pragma unroll
        for (int mi = 0; mi < MI; mi++)
            #pragma unroll
            for (int ni = 0; ni < NI; ni++) {
                MMA16816(acc[mi][ni], ah[mi], bh[ni]);
                MMA16816(acc[mi][ni], ah[mi], bl[ni]);
                MMA16816(acc[mi][ni], al[mi], bh[ni]);
            }
    }
}

// PV pass with register A-fragments: 4 k16-chunks, 8 dh n8-tiles, V smem RS=144
__device__ __forceinline__ void pv_pass(float (*accO)[4], const uint32_t (*af)[4],
                                        uint32_t sV, int lane) {
    #pragma unroll
    for (int kb = 0; kb < 4; kb++) {
        uint32_t b[8][2];
        #pragma unroll
        for (int nb = 0; nb < 4; nb++) {
            uint32_t ad = sV + (uint32_t)((nb * 16 + ((lane >> 4) << 3) + (lane & 7)) * 144
                                          + kb * 32 + (((lane >> 3) & 1) << 4));
            uint32_t r0, r1, r2, r3;
            LDSM_X4(r0, r1, r2, r3, ad);
            b[2 * nb][0] = r0; b[2 * nb][1] = r1;
            b[2 * nb + 1][0] = r2; b[2 * nb + 1][1] = r3;
        }
        #pragma unroll
        for (int ni = 0; ni < 8; ni++)
            MMA16816(accO[ni], af[kb], b[ni]);
    }
}

// ---------------- GEMM core (double-buffered cp.async, BK=32, 2 CTAs/SM) ----
#define GSTG 40960
#define GSM  81920

__device__ __forceinline__ void gemm_issue(uint32_t sb, int stage,
                                           const bf16* Ah, const bf16* Al,
                                           const bf16* Bh, const bf16* Bl,
                                           int K, int m0, int n0, int c) {
    uint32_t st = sb + stage * GSTG;
    const size_t ao = (size_t)m0 * K + c * 32, bo = (size_t)n0 * K + c * 32;
    cpa_tile32(st,         Ah + ao, K);
    cpa_tile32(st + 10240, Al + ao, K);
    cpa_tile32(st + 20480, Bh + bo, K);
    cpa_tile32(st + 30720, Bl + bo, K);
    CPCOMMIT();
}

__device__ __forceinline__ void gemm_core(float (*acc)[4][4],
                                          const bf16* Ah, const bf16* Al,
                                          const bf16* Bh, const bf16* Bl,
                                          int K, int m0, int n0,
                                          uint32_t sb, int lane, int wm, int wn) {
    const int nc = K / 32;
    gemm_issue(sb, 0, Ah, Al, Bh, Bl, K, m0, n0, 0);
    for (int c = 0; c < nc; c++) {
        if (c + 1 < nc) {
            gemm_issue(sb, (c + 1) & 1, Ah, Al, Bh, Bl, K, m0, n0, c + 1);
            CPWAIT1();
        } else CPWAIT0();
        __syncthreads();
        uint32_t st = sb + (c & 1) * GSTG;
        mma_pass3<4, 4, 2, 80>(acc, st, st + 10240, st + 20480, st + 30720, lane, wm, wn);
        __syncthreads();
    }
}

__global__ __launch_bounds__(256, 2) void k_gemm_bf(const bf16* __restrict__ Ah,
                                                    const bf16* __restrict__ Al,
                                                    const bf16* __restrict__ Bh,
                                                    const bf16* __restrict__ Bl,
                                                    bf16* __restrict__ Ch,
                                                    bf16* __restrict__ Cl, int K, int N) {
    extern __shared__ char smem[];
    uint32_t sb = smem_u32(smem);
    const int tid = threadIdx.x, lane = tid & 31, wid = tid >> 5;
    const int m0 = blockIdx.y * 128, n0 = blockIdx.x * 128;
    const int wm = (wid >> 2) * 64, wn = (wid & 3) * 32;

    float acc[4][4][4];
    #pragma unroll
    for (int i = 0; i < 4; i++)
        #pragma unroll
        for (int j = 0; j < 4; j++)
            #pragma unroll
            for (int q = 0; q < 4; q++) acc[i][j][q] = 0.f;

    gemm_core(acc, Ah, Al, Bh, Bl, K, m0, n0, sb, lane, wm, wn);

    #pragma unroll
    for (int mi = 0; mi < 4; mi++) {
        int r = m0 + wm + mi * 16 + (lane >> 2);
        #pragma unroll
        for (int ni = 0; ni < 4; ni++) {
            int c = n0 + wn + ni * 8 + (lane & 3) * 2;
            st_split2(Ch, Cl, (size_t)r * N + c, acc[mi][ni][0], acc[mi][ni][1]);
            st_split2(Ch, Cl, (size_t)(r + 8) * N + c, acc[mi][ni][2], acc[mi][ni][3]);
        }
    }
}

// ---------------- fused O-proj + W-normalize (block-level dispatch) ---------
// even blocks: o-proj 128x128 tile (tensor-bound)
// odd blocks : normalize 256 strided W rows by 1/l (DRAM-bound)
__global__ __launch_bounds__(256, 2) void k_oproj_ws(const bf16* __restrict__ Ah,
                                                     const bf16* __restrict__ Al,
                                                     const bf16* __restrict__ Bh,
                                                     const bf16* __restrict__ Bl,
                                                     const float* __restrict__ bias,
                                                     float* __restrict__ C,
                                                     float* __restrict__ w,
                                                     const float* __restrict__ lg) {
    const int bid = blockIdx.x;
    if (bid & 1) {
        // ---- W normalization: rows g, g+256, ..., 256 rows total ----
        const int g = bid >> 1;
        for (int rr = 0; rr < 256; rr++) {
            int row = g + 256 * rr;
            float il = 1.f / lg[row];
            int r = row & (Tt - 1);
            int n4 = ((r >> 7) + 1) * 32;       // float4 count (tile-aligned prefix)
            float4* p = (float4*)(w + (size_t)row * Tt);
            for (int e = threadIdx.x; e < n4; e += 256) {
                float4 v = p[e];
                v.x *= il; v.y *= il; v.z *= il; v.w *= il;
                p[e] = v;
            }
        }
        return;
    }

    // ---- o-proj tile ----
    extern __shared__ char smem[];
    uint32_t sb = smem_u32(smem);
    const int tid = threadIdx.x, lane = tid & 31, wid = tid >> 5;
    const int tile = bid >> 1;                  // 0..255
    const int m0 = (tile >> 3) * 128, n0 = (tile & 7) * 128;
    const int wm = (wid >> 2) * 64, wn = (wid & 3) * 32;

    float acc[4][4][4];
    #pragma unroll
    for (int i = 0; i < 4; i++)
        #pragma unroll
        for (int j = 0; j < 4; j++)
            #pragma unroll
            for (int q = 0; q < 4; q++) acc[i][j][q] = 0.f;

    gemm_core(acc, Ah, Al, Bh, Bl, Dd, m0, n0, sb, lane, wm, wn);

    #pragma unroll
    for (int mi = 0; mi < 4; mi++) {
        int r = m0 + wm + mi * 16 + (lane >> 2);
        #pragma unroll
        for (int ni = 0; ni < 4; ni++) {
            int c = n0 + wn + ni * 8 + (lane & 3) * 2;
            float bx = bias[c], by = bias[c + 1];
            *(float2*)&C[(size_t)r * Dd + c] =
                make_float2(acc[mi][ni][0] + bx, acc[mi][ni][1] + by);
            *(float2*)&C[(size_t)(r + 8) * Dd + c] =
                make_float2(acc[mi][ni][2] + bx, acc[mi][ni][3] + by);
        }
    }
}

// ---------------- fused causal attention (single-pass, deferred normalize) --
#define SQH 0
#define SQL 18432
#define SKB 36864
#define SVB 110592
#define ASM 184320

__global__ __launch_bounds__(256) void k_attn(const bf16* __restrict__ qkvh,
                                              const bf16* __restrict__ qkvl,
                                              const bf16* __restrict__ vth,
                                              const bf16* __restrict__ vtl,
                                              float* __restrict__ wts,
                                              float* __restrict__ lg,
                                              bf16* __restrict__ atth,
                                              bf16* __restrict__ attl) {
    extern __shared__ char smem[];
    uint32_t sb = smem_u32(smem);

    const int tid = threadIdx.x, lane = tid & 31, wid = tid >> 5;
    const int i = 15 - blockIdx.x;            // heavy tiles first
    const int bh = blockIdx.y, b = bh >> 4, h = bh & 15;
    float* wbase = wts + ((size_t)bh * Tt + i * 128) * Tt;

    const bf16* qb_h = qkvh + ((size_t)b * Tt + i * 128) * D3 + h * 64;
    const bf16* qb_l = qkvl + ((size_t)b * Tt + i * 128) * D3 + h * 64;
    const bf16* kbase_h = qkvh + (size_t)b * Tt * D3 + Dd + h * 64;
    const bf16* kbase_l = qkvl + (size_t)b * Tt * D3 + Dd + h * 64;
    const bf16* vb_h = vth + (size_t)bh * 64 * Tt;
    const bf16* vb_l = vtl + (size_t)bh * 64 * Tt;

    const int wm = wid * 16;                  // warp's 16-row strip
    const int g = lane >> 2, qq = lane & 3;
    const int r0 = wm + g;                    // local row (and r0+8)

    // Q (group), K0 (group), V0 (group)
    cpa_tile(sb + SQH, qb_h, D3, 128);
    cpa_tile(sb + SQL, qb_l, D3, 128);
    CPCOMMIT();
    cpa_tile(sb + SKB,         kbase_h, D3, 128);
    cpa_tile(sb + SKB + 18432, kbase_l, D3, 128);
    CPCOMMIT();
    cpa_tile(sb + SVB,         vb_h,      Tt, 64);
    cpa_tile(sb + SVB + 9216,  vb_l,      Tt, 64);
    cpa_tile(sb + SVB + 18432, vb_h + 64, Tt, 64);
    cpa_tile(sb + SVB + 27648, vb_l + 64, Tt, 64);
    CPCOMMIT();

    // overlap: zero causal tail
    {
        int tail0 = (i + 1) * 128;
        int n4 = (Tt - tail0) >> 2;
        for (int e = tid; e < 128 * n4; e += 256) {
            int row = e / n4, c4 = e % n4;
            *(float4*)(wbase + (size_t)row * Tt + tail0 + c4 * 4) =
                make_float4(0.f, 0.f, 0.f, 0.f);
        }
    }

    float l0 = 0.f, l1 = 0.f;
    float accO[8][4];
    #pragma unroll
    for (int ni = 0; ni < 8; ni++)
        #pragma unroll
        for (int q = 0; q < 4; q++) accO[ni][q] = 0.f;

    // ---- single loop: S -> exp -> W + reg-P -> PV ----
    for (int kt = 0; kt <= i; kt++) {
        if (kt < i) {
            uint32_t stk = sb + SKB + ((kt + 1) & 1) * 36864;
            cpa_tile(stk,         kbase_h + (size_t)(kt + 1) * 128 * D3, D3, 128);
            cpa_tile(stk + 18432, kbase_l + (size_t)(kt + 1) * 128 * D3, D3, 128);
            CPCOMMIT();
            uint32_t stv = sb + SVB + ((kt + 1) & 1) * 36864;
            cpa_tile(stv,         vb_h + (kt + 1) * 128,      Tt, 64);
            cpa_tile(stv + 9216,  vb_l + (kt + 1) * 128,      Tt, 64);
            cpa_tile(stv + 18432, vb_h + (kt + 1) * 128 + 64, Tt, 64);
            cpa_tile(stv + 27648, vb_l + (kt + 1) * 128 + 64, Tt, 64);
            CPCOMMIT();
            CPWAIT2();                        // K_kt, V_kt (and older) ready
        } else CPWAIT0();
        __syncthreads();

        uint32_t stK = sb + SKB + (kt & 1) * 36864;
        uint32_t stV = sb + SVB + (kt & 1) * 36864;

        float accS[1][16][4];
        #pragma unroll
        for (int ni = 0; ni < 16; ni++)
            #pragma unroll
            for (int q = 0; q < 4; q++) accS[0][ni][q] = 0.f;
        mma_pass<1, 16, 4, 144>(accS, sb + SQH, stK,         lane, wm, 0);
        mma_pass<1, 16, 4, 144>(accS, sb + SQH, stK + 18432, lane, wm, 0);
        mma_pass<1, 16, 4, 144>(accS, sb + SQL, stK,         lane, wm, 0);

        // exp, unnormalized W write, register P fragments, l accumulation
        uint32_t phi[8][4], plo[8][4];
        #pragma unroll
        for (int ni = 0; ni < 16; ni++) {
            int c = ni * 8 + qq * 2;
            float v0 = accS[0][ni][0] * 0.125f, v1 = accS[0][ni][1] * 0.125f;
            float v2 = accS[0][ni][2] * 0.125f, v3 = accS[0][ni][3] * 0.125f;
            if (kt == i) {
                if (c     > r0)     v0 = -INFINITY;
                if (c + 1 > r0)     v1 = -INFINITY;
                if (c     > r0 + 8) v2 = -INFINITY;
                if (c + 1 > r0 + 8) v3 = -INFINITY;
            }
            float p0 = __expf(v0), p1 = __expf(v1);
            float p2 = __expf(v2), p3 = __expf(v3);
            l0 += p0 + p1;
            l1 += p2 + p3;
            *(float2*)&wbase[(size_t)r0 * Tt + kt * 128 + c] = make_float2(p0, p1);
            *(float2*)&wbase[(size_t)(r0 + 8) * Tt + kt * 128 + c] = make_float2(p2, p3);
            int kb = ni >> 1, hf = (ni & 1) << 1;
            split2r(p0, p1, phi[kb][hf],     plo[kb][hf]);
            split2r(p2, p3, phi[kb][hf + 1], plo[kb][hf + 1]);
        }

        #pragma unroll
        for (int cchunk = 0; cchunk < 2; cchunk++) {
            uint32_t svh = stV + cchunk * 18432;
            pv_pass(accO, phi + 4 * cchunk, svh,        lane);
            pv_pass(accO, phi + 4 * cchunk, svh + 9216, lane);
            pv_pass(accO, plo + 4 * cchunk, svh,        lane);
        }
        __syncthreads();   // protect stage reuse
    }

    // finish row sums within lane-quads, export l, normalize O
    l0 += __shfl_xor_sync(0xffffffffu, l0, 1);
    l0 += __shfl_xor_sync(0xffffffffu, l0, 2);
    l1 += __shfl_xor_sync(0xffffffffu, l1, 1);
    l1 += __shfl_xor_sync(0xffffffffu, l1, 2);
    if (qq == 0) {
        lg[(size_t)bh * Tt + i * 128 + r0]     = l0;
        lg[(size_t)bh * Tt + i * 128 + r0 + 8] = l1;
    }
    const float il0 = 1.f / l0, il1 = 1.f / l1;

    {
        int q0 = i * 128 + r0;
        size_t base0 = ((size_t)b * Tt + q0) * Dd + h * 64;
        size_t base8 = base0 + (size_t)8 * Dd;
        #pragma unroll
        for (int ni = 0; ni < 8; ni++) {
            int c = ni * 8 + qq * 2;
            st_split2(atth, attl, base0 + c, accO[ni][0] * il0, accO[ni][1] * il0);
            st_split2(atth, attl, base8 + c, accO[ni][2] * il1, accO[ni][3] * il1);
        }
    }
}

// ---------------- merged prepasses (block-level dispatch) ----------------
// blocks [0,3072): Wqkv transpose-split; [3072,4096): Wo; [4096,8192): x split
__global__ __launch_bounds__(256) void k_preconv(const float* __restrict__ Wqkv,
                                                 const float* __restrict__ Wo,
                                                 const float* __restrict__ X,
                                                 bf16* __restrict__ wth, bf16* __restrict__ wtl,
                                                 bf16* __restrict__ woth, bf16* __restrict__ wotl,
                                                 bf16* __restrict__ xh, bf16* __restrict__ xl) {
    const int bid = blockIdx.x;
    if (bid >= 4096) {
        int idx = (bid - 4096) * 256 + threadIdx.x;
        float4 v = ((const float4*)X)[idx];
        bf16 h0 = __float2bfloat16(v.x), h1 = __float2bfloat16(v.y);
        bf16 h2 = __float2bfloat16(v.z), h3 = __float2bfloat16(v.w);
        ((uint64_t*)xh)[idx] = pack4(h0, h1, h2, h3);
        ((uint64_t*)xl)[idx] = pack4(__float2bfloat16(v.x - __bfloat162float(h0)),
                                     __float2bfloat16(v.y - __bfloat162float(h1)),
                                     __float2bfloat16(v.z - __bfloat162float(h2)),
                                     __float2bfloat16(v.w - __bfloat162float(h3)));
        return;
    }
    __shared__ float tile[32][33];
    const float* W; bf16 *hi, *lo; int K, N, n0, k0;
    if (bid < 3072) {
        W = Wqkv; hi = wth; lo = wtl; K = Dd; N = D3;
        n0 = (bid % 96) * 32; k0 = (bid / 96) * 32;
    } else {
        int b2 = bid - 3072;
        W = Wo; hi = woth; lo = wotl; K = Dd; N = Dd;
        n0 = (b2 & 31) * 32; k0 = (b2 >> 5) * 32;
    }
    const int tx = threadIdx.x & 31, ty = threadIdx.x >> 5;
    for (int r = ty; r < 32; r += 8) tile[r][tx] = W[(size_t)(k0 + r) * N + n0 + tx];
    __syncthreads();
    for (int r = ty; r < 32; r += 8) {
        float v = tile[tx][r];
        size_t o = (size_t)(n0 + r) * K + k0 + tx;
        bf16 h = __float2bfloat16(v);
        hi[o] = h;
        lo[o] = __float2bfloat16(v - __bfloat162float(h));
    }
}

__global__ __launch_bounds__(256) void k_conv_vt(const bf16* __restrict__ qh,
                                                 const bf16* __restrict__ ql,
                                                 bf16* __restrict__ hi, bf16* __restrict__ lo) {
    __shared__ bf16 th[32][33], tl[32][33];
    const int bh = blockIdx.z, b = bh >> 4, h = bh & 15;
    const int t0 = blockIdx.x * 32, d0 = blockIdx.y * 32;
    const int tx = threadIdx.x & 31, ty = threadIdx.x >> 5;
    const size_t sbase = ((size_t)b * Tt + t0) * D3 + 2 * Dd + h * 64 + d0;
    for (int r = ty; r < 32; r += 8) {
        th[r][tx] = qh[sbase + (size_t)r * D3 + tx];
        tl[r][tx] = ql[sbase + (size_t)r * D3 + tx];
    }
    __syncthreads();
    bf16* oh = hi + (size_t)bh * 64 * Tt;
    bf16* ol = lo + (size_t)bh * 64 * Tt;
    for (int r = ty; r < 32; r += 8) {
        size_t o = (size_t)(d0 + r) * Tt + t0 + tx;
        oh[o] = th[tx][r];
        ol[o] = tl[tx][r];
    }
}

// ---------------------------------------------------------------------------
extern "C" void kernel_launch(void* const* d_in, const int* in_sizes, int n_in,
                              void* d_out, int out_size) {
    const float* x    = (const float*)d_in[0];
    const float* Wqkv = (const float*)d_in[2];
    const float* Wo   = (const float*)d_in[3];
    const float* bo   = (const float*)d_in[4];

    float* out = (float*)d_out;                 // [B,T,D]
    float* wts = out + (size_t)NT * Dd;         // [B,H,T,T]

    bf16 *qkvh, *qkvl, *xh, *xl, *atth, *attl;
    bf16 *wth, *wtl, *woth, *wotl, *vth, *vtl;
    float* lg;
    cudaGetSymbolAddress((void**)&qkvh, g_qkv_hi);
    cudaGetSymbolAddress((void**)&qkvl, g_qkv_lo);
    cudaGetSymbolAddress((void**)&xh,   g_x_hi);
    cudaGetSymbolAddress((void**)&xl,   g_x_lo);
    cudaGetSymbolAddress((void**)&atth, g_att_hi);
    cudaGetSymbolAddress((void**)&attl, g_att_lo);
    cudaGetSymbolAddress((void**)&wth,  g_wt_hi);
    cudaGetSymbolAddress((void**)&wtl,  g_wt_lo);
    cudaGetSymbolAddress((void**)&woth, g_wot_hi);
    cudaGetSymbolAddress((void**)&wotl, g_wot_lo);
    cudaGetSymbolAddress((void**)&vth,  g_vt_hi);
    cudaGetSymbolAddress((void**)&vtl,  g_vt_lo);
    cudaGetSymbolAddress((void**)&lg,   g_l);

    cudaFuncSetAttribute(k_gemm_bf,  cudaFuncAttributeMaxDynamicSharedMemorySize, GSM);
    cudaFuncSetAttribute(k_oproj_ws, cudaFuncAttributeMaxDynamicSharedMemorySize, GSM);
    cudaFuncSetAttribute(k_attn,     cudaFuncAttributeMaxDynamicSharedMemorySize, ASM);

    // 0) merged prepasses
    k_preconv<<<8192, 256>>>(Wqkv, Wo, x, wth, wtl, woth, wotl, xh, xl);

    // 1) QKV projection -> hi/lo bf16
    k_gemm_bf<<<dim3(D3 / 128, NT / 128), 256, GSM>>>(xh, xl, wth, wtl, qkvh, qkvl, Dd, D3);

    // 2) V transpose
    k_conv_vt<<<dim3(Tt / 32, 2, BHn), 256>>>(qkvh, qkvl, vth, vtl);

    // 3) fused attention (single pass; W unnormalized, l exported)
    k_attn<<<dim3(16, BHn), 256, ASM>>>(qkvh, qkvl, vth, vtl, wts, lg, atth, attl);

    // 4) fused O projection + W normalization (overlapped in one launch)
    k_oproj_ws<<<512, 256, GSM>>>(atth, attl, woth, wotl, bo, out, wts, lg);
}

// round 14
// speedup vs baseline: 1.0689x; 1.0689x over previous
#include <cuda_runtime.h>
#include <cuda_bf16.h>
#include <cstdint>
#include <math.h>

#define Tt 2048
#define Dd 1024
#define Hh 16
#define D3 3072
#define NT 4096      // B*T
#define BHn 32       // B*H

typedef __nv_bfloat16 bf16;

// ---------------- scratch ----------------
__device__ bf16 g_qkv_hi[(size_t)NT * D3];
__device__ bf16 g_qkv_lo[(size_t)NT * D3];
__device__ bf16 g_x_hi[(size_t)NT * Dd];
__device__ bf16 g_x_lo[(size_t)NT * Dd];
__device__ bf16 g_att_hi[(size_t)NT * Dd];
__device__ bf16 g_att_lo[(size_t)NT * Dd];
__device__ bf16 g_wt_hi[(size_t)D3 * Dd];
__device__ bf16 g_wt_lo[(size_t)D3 * Dd];
__device__ bf16 g_wot_hi[(size_t)Dd * Dd];
__device__ bf16 g_wot_lo[(size_t)Dd * Dd];
__device__ bf16 g_vt_hi[(size_t)BHn * 64 * Tt];
__device__ bf16 g_vt_lo[(size_t)BHn * 64 * Tt];

// ---------------- helpers ----------------
__device__ __forceinline__ uint32_t smem_u32(const void* p) {
    uint32_t a;
    asm("{ .reg .u64 t; cvta.to.shared.u64 t, %1; cvt.u32.u64 %0, t; }" : "=r"(a) : "l"(p));
    return a;
}

#define LDSM_X4(r0, r1, r2, r3, a) \
    asm volatile("ldmatrix.sync.aligned.m8n8.x4.shared.b16 {%0,%1,%2,%3}, [%4];" \
                 : "=r"(r0), "=r"(r1), "=r"(r2), "=r"(r3) : "r"(a))

#define MMA16816(c, a, b) \
    asm volatile("mma.sync.aligned.m16n8k16.row.col.f32.bf16.bf16.f32 " \
                 "{%0,%1,%2,%3}, {%4,%5,%6,%7}, {%8,%9}, {%0,%1,%2,%3};" \
                 : "+f"((c)[0]), "+f"((c)[1]), "+f"((c)[2]), "+f"((c)[3]) \
                 : "r"((a)[0]), "r"((a)[1]), "r"((a)[2]), "r"((a)[3]), \
                   "r"((b)[0]), "r"((b)[1]))

#define CP16(dst, src) \
    asm volatile("cp.async.cg.shared.global [%0], [%1], 16;" :: "r"(dst), "l"(src) : "memory")
#define CPCOMMIT() asm volatile("cp.async.commit_group;" ::: "memory")
#define CPWAIT2()  asm volatile("cp.async.wait_group 2;" ::: "memory")
#define CPWAIT1()  asm volatile("cp.async.wait_group 1;" ::: "memory")
#define CPWAIT0()  asm volatile("cp.async.wait_group 0;" ::: "memory")

__device__ __forceinline__ uint64_t pack4(bf16 a, bf16 b, bf16 c, bf16 d) {
    __nv_bfloat162 p0(a, b), p1(c, d);
    uint32_t u0 = *(uint32_t*)&p0, u1 = *(uint32_t*)&p1;
    return ((uint64_t)u1 << 32) | u0;
}

__device__ __forceinline__ void st_split2(bf16* __restrict__ H, bf16* __restrict__ L,
                                          size_t off, float a, float b) {
    bf16 ha = __float2bfloat16(a), hb = __float2bfloat16(b);
    *(__nv_bfloat162*)(H + off) = __nv_bfloat162(ha, hb);
    *(__nv_bfloat162*)(L + off) =
        __nv_bfloat162(__float2bfloat16(a - __bfloat162float(ha)),
                       __float2bfloat16(b - __bfloat162float(hb)));
}

// split a float pair into packed bf16 hi + lo u32 regs
__device__ __forceinline__ void split2r(float a, float b, uint32_t& h, uint32_t& l) {
    bf16 ha = __float2bfloat16(a), hb = __float2bfloat16(b);
    __nv_bfloat162 H(ha, hb);
    h = *(uint32_t*)&H;
    __nv_bfloat162 L(__float2bfloat16(a - __bfloat162float(ha)),
                     __float2bfloat16(b - __bfloat162float(hb)));
    l = *(uint32_t*)&L;
}

// async-copy a rows x 64 bf16 tile into padded smem (144B rows)
__device__ __forceinline__ void cpa_tile(uint32_t s_dst, const bf16* __restrict__ src,
                                         int stride, int rows) {
    for (int e = threadIdx.x; e < rows * 8; e += 256) {
        int r = e >> 3, c = e & 7;
        CP16(s_dst + (uint32_t)(r * 144 + c * 16), src + (size_t)r * stride + c * 8);
    }
}

// async-copy a 128 x 32 bf16 tile into padded smem (80B rows)
__device__ __forceinline__ void cpa_tile32(uint32_t s_dst, const bf16* __restrict__ src,
                                           int stride) {
    for (int e = threadIdx.x; e < 128 * 4; e += 256) {
        int r = e >> 2, c = e & 3;
        CP16(s_dst + (uint32_t)(r * 80 + c * 16), src + (size_t)r * stride + c * 8);
    }
}

// generic pass; RS = smem row stride bytes
template<int MI, int NI, int NKB, int RS>
__device__ __forceinline__ void mma_pass(float (*acc)[NI][4], uint32_t sA, uint32_t sB,
                                         int lane, int m0, int n0) {
    #pragma unroll
    for (int kb = 0; kb < NKB; kb++) {
        uint32_t a[MI][4];
        #pragma unroll
        for (int mi = 0; mi < MI; mi++) {
            uint32_t ad = sA + (uint32_t)((m0 + mi * 16 + (lane & 15)) * RS
                                          + kb * 32 + ((lane >> 4) << 4));
            LDSM_X4(a[mi][0], a[mi][1], a[mi][2], a[mi][3], ad);
        }
        uint32_t b[NI][2];
        #pragma unroll
        for (int nb = 0; nb < NI / 2; nb++) {
            uint32_t ad = sB + (uint32_t)((n0 + nb * 16 + ((lane >> 4) << 3) + (lane & 7)) * RS
                                          + kb * 32 + (((lane >> 3) & 1) << 4));
            uint32_t r0, r1, r2, r3;
            LDSM_X4(r0, r1, r2, r3, ad);
            b[2 * nb][0] = r0; b[2 * nb][1] = r1;
            b[2 * nb + 1][0] = r2; b[2 * nb + 1][1] = r3;
        }
        #pragma unroll
        for (int mi = 0; mi < MI; mi++)
            #pragma unroll
            for (int ni = 0; ni < NI; ni++)
                MMA16816(acc[mi][ni], a[mi], b[ni]);
    }
}

// fused hi/lo pass: load Ah/Al/Bh/Bl fragments once, 3 MMAs per (mi,ni)
template<int MI, int NI, int NKB, int RS>
__device__ __forceinline__ void mma_pass3(float (*acc)[NI][4],
                                          uint32_t sAh, uint32_t sAl,
                                          uint32_t sBh, uint32_t sBl,
                                          int lane, int m0, int n0) {
    #pragma unroll
    for (int kb = 0; kb < NKB; kb++) {
        uint32_t ah[MI][4], al[MI][4];
        #pragma unroll
        for (int mi = 0; mi < MI; mi++) {
            uint32_t off = (uint32_t)((m0 + mi * 16 + (lane & 15)) * RS
                                      + kb * 32 + ((lane >> 4) << 4));
            LDSM_X4(ah[mi][0], ah[mi][1], ah[mi][2], ah[mi][3], sAh + off);
            LDSM_X4(al[mi][0], al[mi][1], al[mi][2], al[mi][3], sAl + off);
        }
        uint32_t bh[NI][2], bl[NI][2];
        #pragma unroll
        for (int nb = 0; nb < NI / 2; nb++) {
            uint32_t off = (uint32_t)((n0 + nb * 16 + ((lane >> 4) << 3) + (lane & 7)) * RS
                                      + kb * 32 + (((lane >> 3) & 1) << 4));
            uint32_t r0, r1, r2, r3;
            LDSM_X4(r0, r1, r2, r3, sBh + off);
            bh[2 * nb][0] = r0; bh[2 * nb][1] = r1;
            bh[2 * nb + 1][0] = r2; bh[2 * nb + 1][1] = r3;
            LDSM_X4(r0, r1, r2, r3, sBl + off);
            bl[2 * nb][0] = r0; bl[2 * nb][1] = r1;
            bl[2 * nb + 1][0] = r2; bl[2 * nb + 1][1] = r3;
        }
        #pragma unroll
        for (int mi = 0; mi < MI; mi++)
            #pragma unroll
            for (int ni = 0; ni < NI; ni++) {
                MMA16816(acc[mi][ni], ah[mi], bh[ni]);
                MMA16816(acc[mi][ni], ah[mi], bl[ni]);
                MMA16816(acc[mi][ni], al[mi], bh[ni]);
            }
    }
}

// PV pass with register A-fragments: 4 k16-chunks, 8 dh n8-tiles, V smem RS=144
__device__ __forceinline__ void pv_pass(float (*accO)[4], const uint32_t (*af)[4],
                                        uint32_t sV, int lane) {
    #pragma unroll
    for (int kb = 0; kb < 4; kb++) {
        uint32_t b[8][2];
        #pragma unroll
        for (int nb = 0; nb < 4; nb++) {
            uint32_t ad = sV + (uint32_t)((nb * 16 + ((lane >> 4) << 3) + (lane & 7)) * 144
                                          + kb * 32 + (((lane >> 3) & 1) << 4));
            uint32_t r0, r1, r2, r3;
            LDSM_X4(r0, r1, r2, r3, ad);
            b[2 * nb][0] = r0; b[2 * nb][1] = r1;
            b[2 * nb + 1][0] = r2; b[2 * nb + 1][1] = r3;
        }
        #pragma unroll
        for (int ni = 0; ni < 8; ni++)
            MMA16816(accO[ni], af[kb], b[ni]);
    }
}

// ---------------- GEMM core (double-buffered cp.async, BK=32, 2 CTAs/SM) ----
#define GSTG 40960
#define GSM  81920

__device__ __forceinline__ void gemm_issue(uint32_t sb, int stage,
                                           const bf16* Ah, const bf16* Al,
                                           const bf16* Bh, const bf16* Bl,
                                           int K, int m0, int n0, int c) {
    uint32_t st = sb + stage * GSTG;
    const size_t ao = (size_t)m0 * K + c * 32, bo = (size_t)n0 * K + c * 32;
    cpa_tile32(st,         Ah + ao, K);
    cpa_tile32(st + 10240, Al + ao, K);
    cpa_tile32(st + 20480, Bh + bo, K);
    cpa_tile32(st + 30720, Bl + bo, K);
    CPCOMMIT();
}

__device__ __forceinline__ void gemm_core(float (*acc)[4][4],
                                          const bf16* Ah, const bf16* Al,
                                          const bf16* Bh, const bf16* Bl,
                                          int K, int m0, int n0,
                                          uint32_t sb, int lane, int wm, int wn) {
    const int nc = K / 32;
    gemm_issue(sb, 0, Ah, Al, Bh, Bl, K, m0, n0, 0);
    for (int c = 0; c < nc; c++) {
        if (c + 1 < nc) {
            gemm_issue(sb, (c + 1) & 1, Ah, Al, Bh, Bl, K, m0, n0, c + 1);
            CPWAIT1();
        } else CPWAIT0();
        __syncthreads();
        uint32_t st = sb + (c & 1) * GSTG;
        mma_pass3<4, 4, 2, 80>(acc, st, st + 10240, st + 20480, st + 30720, lane, wm, wn);
        __syncthreads();
    }
}

__global__ __launch_bounds__(256, 2) void k_gemm_bf(const bf16* __restrict__ Ah,
                                                    const bf16* __restrict__ Al,
                                                    const bf16* __restrict__ Bh,
                                                    const bf16* __restrict__ Bl,
                                                    bf16* __restrict__ Ch,
                                                    bf16* __restrict__ Cl, int K, int N) {
    extern __shared__ char smem[];
    uint32_t sb = smem_u32(smem);
    const int tid = threadIdx.x, lane = tid & 31, wid = tid >> 5;
    const int m0 = blockIdx.y * 128, n0 = blockIdx.x * 128;
    const int wm = (wid >> 2) * 64, wn = (wid & 3) * 32;

    float acc[4][4][4];
    #pragma unroll
    for (int i = 0; i < 4; i++)
        #pragma unroll
        for (int j = 0; j < 4; j++)
            #pragma unroll
            for (int q = 0; q < 4; q++) acc[i][j][q] = 0.f;

    gemm_core(acc, Ah, Al, Bh, Bl, K, m0, n0, sb, lane, wm, wn);

    #pragma unroll
    for (int mi = 0; mi < 4; mi++) {
        int r = m0 + wm + mi * 16 + (lane >> 2);
        #pragma unroll
        for (int ni = 0; ni < 4; ni++) {
            int c = n0 + wn + ni * 8 + (lane & 3) * 2;
            st_split2(Ch, Cl, (size_t)r * N + c, acc[mi][ni][0], acc[mi][ni][1]);
            st_split2(Ch, Cl, (size_t)(r + 8) * N + c, acc[mi][ni][2], acc[mi][ni][3]);
        }
    }
}

__global__ __launch_bounds__(256, 2) void k_gemm_f32(const bf16* __restrict__ Ah,
                                                     const bf16* __restrict__ Al,
                                                     const bf16* __restrict__ Bh,
                                                     const bf16* __restrict__ Bl,
                                                     const float* __restrict__ bias,
                                                     float* __restrict__ C, int K, int N) {
    extern __shared__ char smem[];
    uint32_t sb = smem_u32(smem);
    const int tid = threadIdx.x, lane = tid & 31, wid = tid >> 5;
    const int m0 = blockIdx.y * 128, n0 = blockIdx.x * 128;
    const int wm = (wid >> 2) * 64, wn = (wid & 3) * 32;

    float acc[4][4][4];
    #pragma unroll
    for (int i = 0; i < 4; i++)
        #pragma unroll
        for (int j = 0; j < 4; j++)
            #pragma unroll
            for (int q = 0; q < 4; q++) acc[i][j][q] = 0.f;

    gemm_core(acc, Ah, Al, Bh, Bl, K, m0, n0, sb, lane, wm, wn);

    #pragma unroll
    for (int mi = 0; mi < 4; mi++) {
        int r = m0 + wm + mi * 16 + (lane >> 2);
        #pragma unroll
        for (int ni = 0; ni < 4; ni++) {
            int c = n0 + wn + ni * 8 + (lane & 3) * 2;
            float bx = bias[c], by = bias[c + 1];
            *(float2*)&C[(size_t)r * N + c] =
                make_float2(acc[mi][ni][0] + bx, acc[mi][ni][1] + by);
            *(float2*)&C[(size_t)(r + 8) * N + c] =
                make_float2(acc[mi][ni][2] + bx, acc[mi][ni][3] + by);
        }
    }
}

// ---------------- fused causal attention (single-pass + in-kernel W scale) --
// One loop over K tiles: S (3-pass) -> p=exp(s) -> unnormalized W write +
// register P fragments -> PV accumulate. l in registers; O scaled by 1/l;
// then THIS block normalizes its own W strip (il broadcast via smem).
// smem: Qh @0, Ql @18432; K stages @36864 (+stg*36864; hi +0, lo +18432);
//       V stages @110592 (+stg*36864)
#define SQH 0
#define SQL 18432
#define SKB 36864
#define SVB 110592
#define ASM 184320

__global__ __launch_bounds__(256) void k_attn(const bf16* __restrict__ qkvh,
                                              const bf16* __restrict__ qkvl,
                                              const bf16* __restrict__ vth,
                                              const bf16* __restrict__ vtl,
                                              float* __restrict__ wts,
                                              bf16* __restrict__ atth,
                                              bf16* __restrict__ attl) {
    extern __shared__ char smem[];
    uint32_t sb = smem_u32(smem);

    const int tid = threadIdx.x, lane = tid & 31, wid = tid >> 5;
    const int i = 15 - blockIdx.x;            // heavy tiles first
    const int bh = blockIdx.y, b = bh >> 4, h = bh & 15;
    float* wbase = wts + ((size_t)bh * Tt + i * 128) * Tt;

    const bf16* qb_h = qkvh + ((size_t)b * Tt + i * 128) * D3 + h * 64;
    const bf16* qb_l = qkvl + ((size_t)b * Tt + i * 128) * D3 + h * 64;
    const bf16* kbase_h = qkvh + (size_t)b * Tt * D3 + Dd + h * 64;
    const bf16* kbase_l = qkvl + (size_t)b * Tt * D3 + Dd + h * 64;
    const bf16* vb_h = vth + (size_t)bh * 64 * Tt;
    const bf16* vb_l = vtl + (size_t)bh * 64 * Tt;

    const int wm = wid * 16;                  // warp's 16-row strip
    const int g = lane >> 2, qq = lane & 3;
    const int r0 = wm + g;                    // local row (and r0+8)

    // Q (group), K0 (group), V0 (group)
    cpa_tile(sb + SQH, qb_h, D3, 128);
    cpa_tile(sb + SQL, qb_l, D3, 128);
    CPCOMMIT();
    cpa_tile(sb + SKB,         kbase_h, D3, 128);
    cpa_tile(sb + SKB + 18432, kbase_l, D3, 128);
    CPCOMMIT();
    cpa_tile(sb + SVB,         vb_h,      Tt, 64);
    cpa_tile(sb + SVB + 9216,  vb_l,      Tt, 64);
    cpa_tile(sb + SVB + 18432, vb_h + 64, Tt, 64);
    cpa_tile(sb + SVB + 27648, vb_l + 64, Tt, 64);
    CPCOMMIT();

    // overlap: zero causal tail
    {
        int tail0 = (i + 1) * 128;
        int n4 = (Tt - tail0) >> 2;
        for (int e = tid; e < 128 * n4; e += 256) {
            int row = e / n4, c4 = e % n4;
            *(float4*)(wbase + (size_t)row * Tt + tail0 + c4 * 4) =
                make_float4(0.f, 0.f, 0.f, 0.f);
        }
    }

    float l0 = 0.f, l1 = 0.f;
    float accO[8][4];
    #pragma unroll
    for (int ni = 0; ni < 8; ni++)
        #pragma unroll
        for (int q = 0; q < 4; q++) accO[ni][q] = 0.f;

    // ---- single loop: S -> exp -> W + reg-P -> PV ----
    for (int kt = 0; kt <= i; kt++) {
        if (kt < i) {
            uint32_t stk = sb + SKB + ((kt + 1) & 1) * 36864;
            cpa_tile(stk,         kbase_h + (size_t)(kt + 1) * 128 * D3, D3, 128);
            cpa_tile(stk + 18432, kbase_l + (size_t)(kt + 1) * 128 * D3, D3, 128);
            CPCOMMIT();
            uint32_t stv = sb + SVB + ((kt + 1) & 1) * 36864;
            cpa_tile(stv,         vb_h + (kt + 1) * 128,      Tt, 64);
            cpa_tile(stv + 9216,  vb_l + (kt + 1) * 128,      Tt, 64);
            cpa_tile(stv + 18432, vb_h + (kt + 1) * 128 + 64, Tt, 64);
            cpa_tile(stv + 27648, vb_l + (kt + 1) * 128 + 64, Tt, 64);
            CPCOMMIT();
            CPWAIT2();                        // K_kt, V_kt (and older) ready
        } else CPWAIT0();
        __syncthreads();

        uint32_t stK = sb + SKB + (kt & 1) * 36864;
        uint32_t stV = sb + SVB + (kt & 1) * 36864;

        float accS[1][16][4];
        #pragma unroll
        for (int ni = 0; ni < 16; ni++)
            #pragma unroll
            for (int q = 0; q < 4; q++) accS[0][ni][q] = 0.f;
        mma_pass<1, 16, 4, 144>(accS, sb + SQH, stK,         lane, wm, 0);
        mma_pass<1, 16, 4, 144>(accS, sb + SQH, stK + 18432, lane, wm, 0);
        mma_pass<1, 16, 4, 144>(accS, sb + SQL, stK,         lane, wm, 0);

        // exp, unnormalized W write, register P fragments, l accumulation
        uint32_t phi[8][4], plo[8][4];
        #pragma unroll
        for (int ni = 0; ni < 16; ni++) {
            int c = ni * 8 + qq * 2;
            float v0 = accS[0][ni][0] * 0.125f, v1 = accS[0][ni][1] * 0.125f;
            float v2 = accS[0][ni][2] * 0.125f, v3 = accS[0][ni][3] * 0.125f;
            if (kt == i) {
                if (c     > r0)     v0 = -INFINITY;
                if (c + 1 > r0)     v1 = -INFINITY;
                if (c     > r0 + 8) v2 = -INFINITY;
                if (c + 1 > r0 + 8) v3 = -INFINITY;
            }
            float p0 = __expf(v0), p1 = __expf(v1);
            float p2 = __expf(v2), p3 = __expf(v3);
            l0 += p0 + p1;
            l1 += p2 + p3;
            *(float2*)&wbase[(size_t)r0 * Tt + kt * 128 + c] = make_float2(p0, p1);
            *(float2*)&wbase[(size_t)(r0 + 8) * Tt + kt * 128 + c] = make_float2(p2, p3);
            int kb = ni >> 1, hf = (ni & 1) << 1;
            split2r(p0, p1, phi[kb][hf],     plo[kb][hf]);
            split2r(p2, p3, phi[kb][hf + 1], plo[kb][hf + 1]);
        }

        #pragma unroll
        for (int cchunk = 0; cchunk < 2; cchunk++) {
            uint32_t svh = stV + cchunk * 18432;
            pv_pass(accO, phi + 4 * cchunk, svh,        lane);
            pv_pass(accO, phi + 4 * cchunk, svh + 9216, lane);
            pv_pass(accO, plo + 4 * cchunk, svh,        lane);
        }
        __syncthreads();   // protect stage reuse
    }

    // finish row sums within lane-quads
    l0 += __shfl_xor_sync(0xffffffffu, l0, 1);
    l0 += __shfl_xor_sync(0xffffffffu, l0, 2);
    l1 += __shfl_xor_sync(0xffffffffu, l1, 1);
    l1 += __shfl_xor_sync(0xffffffffu, l1, 2);
    const float il0 = 1.f / l0, il1 = 1.f / l1;

    // normalize O -> att hi/lo bf16
    {
        int q0 = i * 128 + r0;
        size_t base0 = ((size_t)b * Tt + q0) * Dd + h * 64;
        size_t base8 = base0 + (size_t)8 * Dd;
        #pragma unroll
        for (int ni = 0; ni < 8; ni++) {
            int c = ni * 8 + qq * 2;
            st_split2(atth, attl, base0 + c, accO[ni][0] * il0, accO[ni][1] * il0);
            st_split2(atth, attl, base8 + c, accO[ni][2] * il1, accO[ni][3] * il1);
        }
    }

    // broadcast il per row via smem (Q region dead now), then scale W strip
    float* sil = (float*)smem;
    if (qq == 0) { sil[r0] = il0; sil[r0 + 8] = il1; }
    __syncthreads();
    {
        const int n4 = (i + 1) * 32;            // float4 per row (causal prefix)
        for (int e = tid; e < 128 * n4; e += 256) {
            int row = e / n4, c4 = e - row * n4;
            float il = sil[row];
            float4* p = (float4*)(wbase + (size_t)row * Tt) + c4;
            float4 v = *p;
            v.x *= il; v.y *= il; v.z *= il; v.w *= il;
            *p = v;
        }
    }
}

// ---------------- prepasses ----------------
__global__ __launch_bounds__(256) void k_conv_x(const float* __restrict__ X,
                                                bf16* __restrict__ hi, bf16* __restrict__ lo,
                                                int n4) {
    int idx = blockIdx.x * 256 + threadIdx.x;
    if (idx >= n4) return;
    float4 v = ((const float4*)X)[idx];
    bf16 h0 = __float2bfloat16(v.x), h1 = __float2bfloat16(v.y);
    bf16 h2 = __float2bfloat16(v.z), h3 = __float2bfloat16(v.w);
    ((uint64_t*)hi)[idx] = pack4(h0, h1, h2, h3);
    ((uint64_t*)lo)[idx] = pack4(__float2bfloat16(v.x - __bfloat162float(h0)),
                                 __float2bfloat16(v.y - __bfloat162float(h1)),
                                 __float2bfloat16(v.z - __bfloat162float(h2)),
                                 __float2bfloat16(v.w - __bfloat162float(h3)));
}

__global__ __launch_bounds__(256) void k_conv_w(const float* __restrict__ W,
                                                bf16* __restrict__ hi, bf16* __restrict__ lo,
                                                int K, int N) {
    __shared__ float tile[32][33];
    const int n0 = blockIdx.x * 32, k0 = blockIdx.y * 32;
    const int tx = threadIdx.x & 31, ty = threadIdx.x >> 5;
    for (int r = ty; r < 32; r += 8) tile[r][tx] = W[(size_t)(k0 + r) * N + n0 + tx];
    __syncthreads();
    for (int r = ty; r < 32; r += 8) {
        float v = tile[tx][r];
        size_t o = (size_t)(n0 + r) * K + k0 + tx;
        bf16 h = __float2bfloat16(v);
        hi[o] = h;
        lo[o] = __float2bfloat16(v - __bfloat162float(h));
    }
}

__global__ __launch_bounds__(256) void k_conv_vt(const bf16* __restrict__ qh,
                                                 const bf16* __restrict__ ql,
                                                 bf16* __restrict__ hi, bf16* __restrict__ lo) {
    __shared__ bf16 th[32][33], tl[32][33];
    const int bh = blockIdx.z, b = bh >> 4, h = bh & 15;
    const int t0 = blockIdx.x * 32, d0 = blockIdx.y * 32;
    const int tx = threadIdx.x & 31, ty = threadIdx.x >> 5;
    const size_t sbase = ((size_t)b * Tt + t0) * D3 + 2 * Dd + h * 64 + d0;
    for (int r = ty; r < 32; r += 8) {
        th[r][tx] = qh[sbase + (size_t)r * D3 + tx];
        tl[r][tx] = ql[sbase + (size_t)r * D3 + tx];
    }
    __syncthreads();
    bf16* oh = hi + (size_t)bh * 64 * Tt;
    bf16* ol = lo + (size_t)bh * 64 * Tt;
    for (int r = ty; r < 32; r += 8) {
        size_t o = (size_t)(d0 + r) * Tt + t0 + tx;
        oh[o] = th[tx][r];
        ol[o] = tl[tx][r];
    }
}

// ---------------------------------------------------------------------------
extern "C" void kernel_launch(void* const* d_in, const int* in_sizes, int n_in,
                              void* d_out, int out_size) {
    const float* x    = (const float*)d_in[0];
    const float* Wqkv = (const float*)d_in[2];
    const float* Wo   = (const float*)d_in[3];
    const float* bo   = (const float*)d_in[4];

    float* out = (float*)d_out;                 // [B,T,D]
    float* wts = out + (size_t)NT * Dd;         // [B,H,T,T]

    bf16 *qkvh, *qkvl, *xh, *xl, *atth, *attl;
    bf16 *wth, *wtl, *woth, *wotl, *vth, *vtl;
    cudaGetSymbolAddress((void**)&qkvh, g_qkv_hi);
    cudaGetSymbolAddress((void**)&qkvl, g_qkv_lo);
    cudaGetSymbolAddress((void**)&xh,   g_x_hi);
    cudaGetSymbolAddress((void**)&xl,   g_x_lo);
    cudaGetSymbolAddress((void**)&atth, g_att_hi);
    cudaGetSymbolAddress((void**)&attl, g_att_lo);
    cudaGetSymbolAddress((void**)&wth,  g_wt_hi);
    cudaGetSymbolAddress((void**)&wtl,  g_wt_lo);
    cudaGetSymbolAddress((void**)&woth, g_wot_hi);
    cudaGetSymbolAddress((void**)&wotl, g_wot_lo);
    cudaGetSymbolAddress((void**)&vth,  g_vt_hi);
    cudaGetSymbolAddress((void**)&vtl,  g_vt_lo);

    cudaFuncSetAttribute(k_gemm_bf,  cudaFuncAttributeMaxDynamicSharedMemorySize, GSM);
    cudaFuncSetAttribute(k_gemm_f32, cudaFuncAttributeMaxDynamicSharedMemorySize, GSM);
    cudaFuncSetAttribute(k_attn,     cudaFuncAttributeMaxDynamicSharedMemorySize, ASM);

    // prepasses
    k_conv_w<<<dim3(D3 / 32, Dd / 32), 256>>>(Wqkv, wth, wtl, Dd, D3);
    k_conv_w<<<dim3(Dd / 32, Dd / 32), 256>>>(Wo, woth, wotl, Dd, Dd);
    k_conv_x<<<(NT * Dd / 4 + 255) / 256, 256>>>(x, xh, xl, NT * Dd / 4);

    // 1) QKV projection -> hi/lo bf16
    k_gemm_bf<<<dim3(D3 / 128, NT / 128), 256, GSM>>>(xh, xl, wth, wtl, qkvh, qkvl, Dd, D3);

    // 2) V transpose
    k_conv_vt<<<dim3(Tt / 32, 2, BHn), 256>>>(qkvh, qkvl, vth, vtl);

    // 3) fused attention (single pass; W normalized in-kernel)
    k_attn<<<dim3(16, BHn), 256, ASM>>>(qkvh, qkvl, vth, vtl, wts, atth, attl);

    // 4) O projection
    k_gemm_f32<<<dim3(Dd / 128, NT / 128), 256, GSM>>>(atth, attl, woth, wotl, bo, out, Dd, Dd);
}

// round 15
// speedup vs baseline: 1.1550x; 1.0806x over previous
#include <cuda_runtime.h>
#include <cuda_bf16.h>
#include <cstdint>
#include <math.h>

#define Tt 2048
#define Dd 1024
#define Hh 16
#define D3 3072
#define NT 4096      // B*T
#define BHn 32       // B*H

typedef __nv_bfloat16 bf16;

// ---------------- scratch ----------------
__device__ bf16 g_qkv_hi[(size_t)NT * D3];
__device__ bf16 g_qkv_lo[(size_t)NT * D3];
__device__ bf16 g_x_hi[(size_t)NT * Dd];
__device__ bf16 g_x_lo[(size_t)NT * Dd];
__device__ bf16 g_att_hi[(size_t)NT * Dd];
__device__ bf16 g_att_lo[(size_t)NT * Dd];
__device__ bf16 g_wt_hi[(size_t)D3 * Dd];
__device__ bf16 g_wt_lo[(size_t)D3 * Dd];
__device__ bf16 g_wot_hi[(size_t)Dd * Dd];
__device__ bf16 g_wot_lo[(size_t)Dd * Dd];
__device__ bf16 g_vt_hi[(size_t)BHn * 64 * Tt];
__device__ bf16 g_vt_lo[(size_t)BHn * 64 * Tt];
__device__ float g_l[(size_t)BHn * Tt];     // row sums (unnormalized)

// ---------------- helpers ----------------
__device__ __forceinline__ uint32_t smem_u32(const void* p) {
    uint32_t a;
    asm("{ .reg .u64 t; cvta.to.shared.u64 t, %1; cvt.u32.u64 %0, t; }" : "=r"(a) : "l"(p));
    return a;
}

#define LDSM_X4(r0, r1, r2, r3, a) \
    asm volatile("ldmatrix.sync.aligned.m8n8.x4.shared.b16 {%0,%1,%2,%3}, [%4];" \
                 : "=r"(r0), "=r"(r1), "=r"(r2), "=r"(r3) : "r"(a))

#define MMA16816(c, a, b) \
    asm volatile("mma.sync.aligned.m16n8k16.row.col.f32.bf16.bf16.f32 " \
                 "{%0,%1,%2,%3}, {%4,%5,%6,%7}, {%8,%9}, {%0,%1,%2,%3};" \
                 : "+f"((c)[0]), "+f"((c)[1]), "+f"((c)[2]), "+f"((c)[3]) \
                 : "r"((a)[0]), "r"((a)[1]), "r"((a)[2]), "r"((a)[3]), \
                   "r"((b)[0]), "r"((b)[1]))

#define CP16(dst, src) \
    asm volatile("cp.async.cg.shared.global [%0], [%1], 16;" :: "r"(dst), "l"(src) : "memory")
#define CPCOMMIT() asm volatile("cp.async.commit_group;" ::: "memory")
#define CPWAIT2()  asm volatile("cp.async.wait_group 2;" ::: "memory")
#define CPWAIT1()  asm volatile("cp.async.wait_group 1;" ::: "memory")
#define CPWAIT0()  asm volatile("cp.async.wait_group 0;" ::: "memory")

__device__ __forceinline__ uint64_t pack4(bf16 a, bf16 b, bf16 c, bf16 d) {
    __nv_bfloat162 p0(a, b), p1(c, d);
    uint32_t u0 = *(uint32_t*)&p0, u1 = *(uint32_t*)&p1;
    return ((uint64_t)u1 << 32) | u0;
}

__device__ __forceinline__ void st_split2(bf16* __restrict__ H, bf16* __restrict__ L,
                                          size_t off, float a, float b) {
    bf16 ha = __float2bfloat16(a), hb = __float2bfloat16(b);
    *(__nv_bfloat162*)(H + off) = __nv_bfloat162(ha, hb);
    *(__nv_bfloat162*)(L + off) =
        __nv_bfloat162(__float2bfloat16(a - __bfloat162float(ha)),
                       __float2bfloat16(b - __bfloat162float(hb)));
}

// split a float pair into packed bf16 hi + lo u32 regs
__device__ __forceinline__ void split2r(float a, float b, uint32_t& h, uint32_t& l) {
    bf16 ha = __float2bfloat16(a), hb = __float2bfloat16(b);
    __nv_bfloat162 H(ha, hb);
    h = *(uint32_t*)&H;
    __nv_bfloat162 L(__float2bfloat16(a - __bfloat162float(ha)),
                     __float2bfloat16(b - __bfloat162float(hb)));
    l = *(uint32_t*)&L;
}

// async-copy a rows x 64 bf16 tile into padded smem (144B rows)
__device__ __forceinline__ void cpa_tile(uint32_t s_dst, const bf16* __restrict__ src,
                                         int stride, int rows) {
    for (int e = threadIdx.x; e < rows * 8; e += 256) {
        int r = e >> 3, c = e & 7;
        CP16(s_dst + (uint32_t)(r * 144 + c * 16), src + (size_t)r * stride + c * 8);
    }
}

// async-copy a 128 x 32 bf16 tile into padded smem (80B rows)
__device__ __forceinline__ void cpa_tile32(uint32_t s_dst, const bf16* __restrict__ src,
                                           int stride) {
    for (int e = threadIdx.x; e < 128 * 4; e += 256) {
        int r = e >> 2, c = e & 3;
        CP16(s_dst + (uint32_t)(r * 80 + c * 16), src + (size_t)r * stride + c * 8);
    }
}

// generic pass; RS = smem row stride bytes
template<int MI, int NI, int NKB, int RS>
__device__ __forceinline__ void mma_pass(float (*acc)[NI][4], uint32_t sA, uint32_t sB,
                                         int lane, int m0, int n0) {
    #pragma unroll
    for (int kb = 0; kb < NKB; kb++) {
        uint32_t a[MI][4];
        #pragma unroll
        for (int mi = 0; mi < MI; mi++) {
            uint32_t ad = sA + (uint32_t)((m0 + mi * 16 + (lane & 15)) * RS
                                          + kb * 32 + ((lane >> 4) << 4));
            LDSM_X4(a[mi][0], a[mi][1], a[mi][2], a[mi][3], ad);
        }
        uint32_t b[NI][2];
        #pragma unroll
        for (int nb = 0; nb < NI / 2; nb++) {
            uint32_t ad = sB + (uint32_t)((n0 + nb * 16 + ((lane >> 4) << 3) + (lane & 7)) * RS
                                          + kb * 32 + (((lane >> 3) & 1) << 4));
            uint32_t r0, r1, r2, r3;
            LDSM_X4(r0, r1, r2, r3, ad);
            b[2 * nb][0] = r0; b[2 * nb][1] = r1;
            b[2 * nb + 1][0] = r2; b[2 * nb + 1][1] = r3;
        }
        #pragma unroll
        for (int mi = 0; mi < MI; mi++)
            #pragma unroll
            for (int ni = 0; ni < NI; ni++)
                MMA16816(acc[mi][ni], a[mi], b[ni]);
    }
}

// fused hi/lo pass: load Ah/Al/Bh/Bl fragments once, 3 MMAs per (mi,ni)
template<int MI, int NI, int NKB, int RS>
__device__ __forceinline__ void mma_pass3(float (*acc)[NI][4],
                                          uint32_t sAh, uint32_t sAl,
                                          uint32_t sBh, uint32_t sBl,
                                          int lane, int m0, int n0) {
    #pragma unroll
    for (int kb = 0; kb < NKB; kb++) {
        uint32_t ah[MI][4], al[MI][4];
        #pragma unroll
        for (int mi = 0; mi < MI; mi++) {
            uint32_t off = (uint32_t)((m0 + mi * 16 + (lane & 15)) * RS
                                      + kb * 32 + ((lane >> 4) << 4));
            LDSM_X4(ah[mi][0], ah[mi][1], ah[mi][2], ah[mi][3], sAh + off);
            LDSM_X4(al[mi][0], al[mi][1], al[mi][2], al[mi][3], sAl + off);
        }
        uint32_t bh[NI][2], bl[NI][2];
        #pragma unroll
        for (int nb = 0; nb < NI / 2; nb++) {
            uint32_t off = (uint32_t)((n0 + nb * 16 + ((lane >> 4) << 3) + (lane & 7)) * RS
                                      + kb * 32 + (((lane >> 3) & 1) << 4));
            uint32_t r0, r1, r2, r3;
            LDSM_X4(r0, r1, r2, r3, sBh + off);
            bh[2 * nb][0] = r0; bh[2 * nb][1] = r1;
            bh[2 * nb + 1][0] = r2; bh[2 * nb + 1][1] = r3;
            LDSM_X4(r0, r1, r2, r3, sBl + off);
            bl[2 * nb][0] = r0; bl[2 * nb][1] = r1;
            bl[2 * nb + 1][0] = r2; bl[2 * nb + 1][1] = r3;
        }
        #pragma unroll
        for (int mi = 0; mi < MI; mi++)
            #pragma unroll
            for (int ni = 0; ni < NI; ni++) {
                MMA16816(acc[mi][ni], ah[mi], bh[ni]);
                MMA16816(acc[mi][ni], ah[mi], bl[ni]);
                MMA16816(acc[mi][ni], al[mi], bh[ni]);
            }
    }
}

// PV pass with register A-fragments: 4 k16-chunks, 8 dh n8-tiles, V smem RS=144
__device__ __forceinline__ void pv_pass(float (*accO)[4], const uint32_t (*af)[4],
                                        uint32_t sV, int lane) {
    #pragma unroll
    for (int kb = 0; kb < 4; kb++) {
        uint32_t b[8][2];
        #pragma unroll
        for (int nb = 0; nb < 4; nb++) {
            uint32_t ad = sV + (uint32_t)((nb * 16 + ((lane >> 4) << 3) + (lane & 7)) * 144
                                          + kb * 32 + (((lane >> 3) & 1) << 4));
            uint32_t r0, r1, r2, r3;
            LDSM_X4(r0, r1, r2, r3, ad);
            b[2 * nb][0] = r0; b[2 * nb][1] = r1;
            b[2 * nb + 1][0] = r2; b[2 * nb + 1][1] = r3;
        }
        #pragma unroll
        for (int ni = 0; ni < 8; ni++)
            MMA16816(accO[ni], af[kb], b[ni]);
    }
}

// ---------------- GEMM core (double-buffered cp.async, BK=32, 2 CTAs/SM) ----
#define GSTG 40960
#define GSM  81920

__device__ __forceinline__ void gemm_issue(uint32_t sb, int stage,
                                           const bf16* Ah, const bf16* Al,
                                           const bf16* Bh, const bf16* Bl,
                                           int K, int m0, int n0, int c) {
    uint32_t st = sb + stage * GSTG;
    const size_t ao = (size_t)m0 * K + c * 32, bo = (size_t)n0 * K + c * 32;
    cpa_tile32(st,         Ah + ao, K);
    cpa_tile32(st + 10240, Al + ao, K);
    cpa_tile32(st + 20480, Bh + bo, K);
    cpa_tile32(st + 30720, Bl + bo, K);
    CPCOMMIT();
}

__device__ __forceinline__ void gemm_core(float (*acc)[4][4],
                                          const bf16* Ah, const bf16* Al,
                                          const bf16* Bh, const bf16* Bl,
                                          int K, int m0, int n0,
                                          uint32_t sb, int lane, int wm, int wn) {
    const int nc = K / 32;
    gemm_issue(sb, 0, Ah, Al, Bh, Bl, K, m0, n0, 0);
    for (int c = 0; c < nc; c++) {
        if (c + 1 < nc) {
            gemm_issue(sb, (c + 1) & 1, Ah, Al, Bh, Bl, K, m0, n0, c + 1);
            CPWAIT1();
        } else CPWAIT0();
        __syncthreads();
        uint32_t st = sb + (c & 1) * GSTG;
        mma_pass3<4, 4, 2, 80>(acc, st, st + 10240, st + 20480, st + 30720, lane, wm, wn);
        __syncthreads();
    }
}

__global__ __launch_bounds__(256, 2) void k_gemm_bf(const bf16* __restrict__ Ah,
                                                    const bf16* __restrict__ Al,
                                                    const bf16* __restrict__ Bh,
                                                    const bf16* __restrict__ Bl,
                                                    bf16* __restrict__ Ch,
                                                    bf16* __restrict__ Cl, int K, int N) {
    extern __shared__ char smem[];
    uint32_t sb = smem_u32(smem);
    const int tid = threadIdx.x, lane = tid & 31, wid = tid >> 5;
    const int m0 = blockIdx.y * 128, n0 = blockIdx.x * 128;
    const int wm = (wid >> 2) * 64, wn = (wid & 3) * 32;

    float acc[4][4][4];
    #pragma unroll
    for (int i = 0; i < 4; i++)
        #pragma unroll
        for (int j = 0; j < 4; j++)
            #pragma unroll
            for (int q = 0; q < 4; q++) acc[i][j][q] = 0.f;

    gemm_core(acc, Ah, Al, Bh, Bl, K, m0, n0, sb, lane, wm, wn);

    #pragma unroll
    for (int mi = 0; mi < 4; mi++) {
        int r = m0 + wm + mi * 16 + (lane >> 2);
        #pragma unroll
        for (int ni = 0; ni < 4; ni++) {
            int c = n0 + wn + ni * 8 + (lane & 3) * 2;
            st_split2(Ch, Cl, (size_t)r * N + c, acc[mi][ni][0], acc[mi][ni][1]);
            st_split2(Ch, Cl, (size_t)(r + 8) * N + c, acc[mi][ni][2], acc[mi][ni][3]);
        }
    }
}

// ---------------- fused O-proj + W-normalize (fine-grained dispatch) --------
// blocks [0,256): o-proj 128x128 tiles (tensor-bound, launched first)
// blocks [256,2304): each scales 32 consecutive W rows by 1/l (small, backfill)
__global__ __launch_bounds__(256, 2) void k_oproj_ws(const bf16* __restrict__ Ah,
                                                     const bf16* __restrict__ Al,
                                                     const bf16* __restrict__ Bh,
                                                     const bf16* __restrict__ Bl,
                                                     const float* __restrict__ bias,
                                                     float* __restrict__ C,
                                                     float* __restrict__ w,
                                                     const float* __restrict__ lg) {
    const int bid = blockIdx.x;
    if (bid >= 256) {
        // ---- W normalization: 32 consecutive rows ----
        const int row0 = (bid - 256) * 32;
        for (int rr = 0; rr < 32; rr++) {
            int row = row0 + rr;
            float il = 1.f / lg[row];
            int r = row & (Tt - 1);
            int n4 = ((r >> 7) + 1) * 32;       // float4 count (tile-aligned prefix)
            float4* p = (float4*)(w + (size_t)row * Tt);
            for (int e = threadIdx.x; e < n4; e += 256) {
                float4 v = p[e];
                v.x *= il; v.y *= il; v.z *= il; v.w *= il;
                p[e] = v;
            }
        }
        return;
    }

    // ---- o-proj tile ----
    extern __shared__ char smem[];
    uint32_t sb = smem_u32(smem);
    const int tid = threadIdx.x, lane = tid & 31, wid = tid >> 5;
    const int m0 = (bid >> 3) * 128, n0 = (bid & 7) * 128;
    const int wm = (wid >> 2) * 64, wn = (wid & 3) * 32;

    float acc[4][4][4];
    #pragma unroll
    for (int i = 0; i < 4; i++)
        #pragma unroll
        for (int j = 0; j < 4; j++)
            #pragma unroll
            for (int q = 0; q < 4; q++) acc[i][j][q] = 0.f;

    gemm_core(acc, Ah, Al, Bh, Bl, Dd, m0, n0, sb, lane, wm, wn);

    #pragma unroll
    for (int mi = 0; mi < 4; mi++) {
        int r = m0 + wm + mi * 16 + (lane >> 2);
        #pragma unroll
        for (int ni = 0; ni < 4; ni++) {
            int c = n0 + wn + ni * 8 + (lane & 3) * 2;
            float bx = bias[c], by = bias[c + 1];
            *(float2*)&C[(size_t)r * Dd + c] =
                make_float2(acc[mi][ni][0] + bx, acc[mi][ni][1] + by);
            *(float2*)&C[(size_t)(r + 8) * Dd + c] =
                make_float2(acc[mi][ni][2] + bx, acc[mi][ni][3] + by);
        }
    }
}

// ---------------- fused causal attention (single-pass, deferred normalize) --
#define SQH 0
#define SQL 18432
#define SKB 36864
#define SVB 110592
#define ASM 184320

__global__ __launch_bounds__(256) void k_attn(const bf16* __restrict__ qkvh,
                                              const bf16* __restrict__ qkvl,
                                              const bf16* __restrict__ vth,
                                              const bf16* __restrict__ vtl,
                                              float* __restrict__ wts,
                                              float* __restrict__ lg,
                                              bf16* __restrict__ atth,
                                              bf16* __restrict__ attl) {
    extern __shared__ char smem[];
    uint32_t sb = smem_u32(smem);

    const int tid = threadIdx.x, lane = tid & 31, wid = tid >> 5;
    const int i = 15 - blockIdx.x;            // heavy tiles first
    const int bh = blockIdx.y, b = bh >> 4, h = bh & 15;
    float* wbase = wts + ((size_t)bh * Tt + i * 128) * Tt;

    const bf16* qb_h = qkvh + ((size_t)b * Tt + i * 128) * D3 + h * 64;
    const bf16* qb_l = qkvl + ((size_t)b * Tt + i * 128) * D3 + h * 64;
    const bf16* kbase_h = qkvh + (size_t)b * Tt * D3 + Dd + h * 64;
    const bf16* kbase_l = qkvl + (size_t)b * Tt * D3 + Dd + h * 64;
    const bf16* vb_h = vth + (size_t)bh * 64 * Tt;
    const bf16* vb_l = vtl + (size_t)bh * 64 * Tt;

    const int wm = wid * 16;                  // warp's 16-row strip
    const int g = lane >> 2, qq = lane & 3;
    const int r0 = wm + g;                    // local row (and r0+8)

    // Q (group), K0 (group), V0 (group)
    cpa_tile(sb + SQH, qb_h, D3, 128);
    cpa_tile(sb + SQL, qb_l, D3, 128);
    CPCOMMIT();
    cpa_tile(sb + SKB,         kbase_h, D3, 128);
    cpa_tile(sb + SKB + 18432, kbase_l, D3, 128);
    CPCOMMIT();
    cpa_tile(sb + SVB,         vb_h,      Tt, 64);
    cpa_tile(sb + SVB + 9216,  vb_l,      Tt, 64);
    cpa_tile(sb + SVB + 18432, vb_h + 64, Tt, 64);
    cpa_tile(sb + SVB + 27648, vb_l + 64, Tt, 64);
    CPCOMMIT();

    // overlap: zero causal tail
    {
        int tail0 = (i + 1) * 128;
        int n4 = (Tt - tail0) >> 2;
        for (int e = tid; e < 128 * n4; e += 256) {
            int row = e / n4, c4 = e % n4;
            *(float4*)(wbase + (size_t)row * Tt + tail0 + c4 * 4) =
                make_float4(0.f, 0.f, 0.f, 0.f);
        }
    }

    float l0 = 0.f, l1 = 0.f;
    float accO[8][4];
    #pragma unroll
    for (int ni = 0; ni < 8; ni++)
        #pragma unroll
        for (int q = 0; q < 4; q++) accO[ni][q] = 0.f;

    // ---- single loop: S -> exp -> W + reg-P -> PV ----
    for (int kt = 0; kt <= i; kt++) {
        if (kt < i) {
            uint32_t stk = sb + SKB + ((kt + 1) & 1) * 36864;
            cpa_tile(stk,         kbase_h + (size_t)(kt + 1) * 128 * D3, D3, 128);
            cpa_tile(stk + 18432, kbase_l + (size_t)(kt + 1) * 128 * D3, D3, 128);
            CPCOMMIT();
            uint32_t stv = sb + SVB + ((kt + 1) & 1) * 36864;
            cpa_tile(stv,         vb_h + (kt + 1) * 128,      Tt, 64);
            cpa_tile(stv + 9216,  vb_l + (kt + 1) * 128,      Tt, 64);
            cpa_tile(stv + 18432, vb_h + (kt + 1) * 128 + 64, Tt, 64);
            cpa_tile(stv + 27648, vb_l + (kt + 1) * 128 + 64, Tt, 64);
            CPCOMMIT();
            CPWAIT2();                        // K_kt, V_kt (and older) ready
        } else CPWAIT0();
        __syncthreads();

        uint32_t stK = sb + SKB + (kt & 1) * 36864;
        uint32_t stV = sb + SVB + (kt & 1) * 36864;

        float accS[1][16][4];
        #pragma unroll
        for (int ni = 0; ni < 16; ni++)
            #pragma unroll
            for (int q = 0; q < 4; q++) accS[0][ni][q] = 0.f;
        mma_pass<1, 16, 4, 144>(accS, sb + SQH, stK,         lane, wm, 0);
        mma_pass<1, 16, 4, 144>(accS, sb + SQH, stK + 18432, lane, wm, 0);
        mma_pass<1, 16, 4, 144>(accS, sb + SQL, stK,         lane, wm, 0);

        // exp, unnormalized W write, register P fragments, l accumulation
        uint32_t phi[8][4], plo[8][4];
        #pragma unroll
        for (int ni = 0; ni < 16; ni++) {
            int c = ni * 8 + qq * 2;
            float v0 = accS[0][ni][0] * 0.125f, v1 = accS[0][ni][1] * 0.125f;
            float v2 = accS[0][ni][2] * 0.125f, v3 = accS[0][ni][3] * 0.125f;
            if (kt == i) {
                if (c     > r0)     v0 = -INFINITY;
                if (c + 1 > r0)     v1 = -INFINITY;
                if (c     > r0 + 8) v2 = -INFINITY;
                if (c + 1 > r0 + 8) v3 = -INFINITY;
            }
            float p0 = __expf(v0), p1 = __expf(v1);
            float p2 = __expf(v2), p3 = __expf(v3);
            l0 += p0 + p1;
            l1 += p2 + p3;
            *(float2*)&wbase[(size_t)r0 * Tt + kt * 128 + c] = make_float2(p0, p1);
            *(float2*)&wbase[(size_t)(r0 + 8) * Tt + kt * 128 + c] = make_float2(p2, p3);
            int kb = ni >> 1, hf = (ni & 1) << 1;
            split2r(p0, p1, phi[kb][hf],     plo[kb][hf]);
            split2r(p2, p3, phi[kb][hf + 1], plo[kb][hf + 1]);
        }

        #pragma unroll
        for (int cchunk = 0; cchunk < 2; cchunk++) {
            uint32_t svh = stV + cchunk * 18432;
            pv_pass(accO, phi + 4 * cchunk, svh,        lane);
            pv_pass(accO, phi + 4 * cchunk, svh + 9216, lane);
            pv_pass(accO, plo + 4 * cchunk, svh,        lane);
        }
        __syncthreads();   // protect stage reuse
    }

    // finish row sums within lane-quads, export l, normalize O
    l0 += __shfl_xor_sync(0xffffffffu, l0, 1);
    l0 += __shfl_xor_sync(0xffffffffu, l0, 2);
    l1 += __shfl_xor_sync(0xffffffffu, l1, 1);
    l1 += __shfl_xor_sync(0xffffffffu, l1, 2);
    if (qq == 0) {
        lg[(size_t)bh * Tt + i * 128 + r0]     = l0;
        lg[(size_t)bh * Tt + i * 128 + r0 + 8] = l1;
    }
    const float il0 = 1.f / l0, il1 = 1.f / l1;

    {
        int q0 = i * 128 + r0;
        size_t base0 = ((size_t)b * Tt + q0) * Dd + h * 64;
        size_t base8 = base0 + (size_t)8 * Dd;
        #pragma unroll
        for (int ni = 0; ni < 8; ni++) {
            int c = ni * 8 + qq * 2;
            st_split2(atth, attl, base0 + c, accO[ni][0] * il0, accO[ni][1] * il0);
            st_split2(atth, attl, base8 + c, accO[ni][2] * il1, accO[ni][3] * il1);
        }
    }
}

// ---------------- prepasses ----------------
__global__ __launch_bounds__(256) void k_conv_x(const float* __restrict__ X,
                                                bf16* __restrict__ hi, bf16* __restrict__ lo,
                                                int n4) {
    int idx = blockIdx.x * 256 + threadIdx.x;
    if (idx >= n4) return;
    float4 v = ((const float4*)X)[idx];
    bf16 h0 = __float2bfloat16(v.x), h1 = __float2bfloat16(v.y);
    bf16 h2 = __float2bfloat16(v.z), h3 = __float2bfloat16(v.w);
    ((uint64_t*)hi)[idx] = pack4(h0, h1, h2, h3);
    ((uint64_t*)lo)[idx] = pack4(__float2bfloat16(v.x - __bfloat162float(h0)),
                                 __float2bfloat16(v.y - __bfloat162float(h1)),
                                 __float2bfloat16(v.z - __bfloat162float(h2)),
                                 __float2bfloat16(v.w - __bfloat162float(h3)));
}

__global__ __launch_bounds__(256) void k_conv_w(const float* __restrict__ W,
                                                bf16* __restrict__ hi, bf16* __restrict__ lo,
                                                int K, int N) {
    __shared__ float tile[32][33];
    const int n0 = blockIdx.x * 32, k0 = blockIdx.y * 32;
    const int tx = threadIdx.x & 31, ty = threadIdx.x >> 5;
    for (int r = ty; r < 32; r += 8) tile[r][tx] = W[(size_t)(k0 + r) * N + n0 + tx];
    __syncthreads();
    for (int r = ty; r < 32; r += 8) {
        float v = tile[tx][r];
        size_t o = (size_t)(n0 + r) * K + k0 + tx;
        bf16 h = __float2bfloat16(v);
        hi[o] = h;
        lo[o] = __float2bfloat16(v - __bfloat162float(h));
    }
}

__global__ __launch_bounds__(256) void k_conv_vt(const bf16* __restrict__ qh,
                                                 const bf16* __restrict__ ql,
                                                 bf16* __restrict__ hi, bf16* __restrict__ lo) {
    __shared__ bf16 th[32][33], tl[32][33];
    const int bh = blockIdx.z, b = bh >> 4, h = bh & 15;
    const int t0 = blockIdx.x * 32, d0 = blockIdx.y * 32;
    const int tx = threadIdx.x & 31, ty = threadIdx.x >> 5;
    const size_t sbase = ((size_t)b * Tt + t0) * D3 + 2 * Dd + h * 64 + d0;
    for (int r = ty; r < 32; r += 8) {
        th[r][tx] = qh[sbase + (size_t)r * D3 + tx];
        tl[r][tx] = ql[sbase + (size_t)r * D3 + tx];
    }
    __syncthreads();
    bf16* oh = hi + (size_t)bh * 64 * Tt;
    bf16* ol = lo + (size_t)bh * 64 * Tt;
    for (int r = ty; r < 32; r += 8) {
        size_t o = (size_t)(d0 + r) * Tt + t0 + tx;
        oh[o] = th[tx][r];
        ol[o] = tl[tx][r];
    }
}

// ---------------------------------------------------------------------------
extern "C" void kernel_launch(void* const* d_in, const int* in_sizes, int n_in,
                              void* d_out, int out_size) {
    const float* x    = (const float*)d_in[0];
    const float* Wqkv = (const float*)d_in[2];
    const float* Wo   = (const float*)d_in[3];
    const float* bo   = (const float*)d_in[4];

    float* out = (float*)d_out;                 // [B,T,D]
    float* wts = out + (size_t)NT * Dd;         // [B,H,T,T]

    bf16 *qkvh, *qkvl, *xh, *xl, *atth, *attl;
    bf16 *wth, *wtl, *woth, *wotl, *vth, *vtl;
    float* lg;
    cudaGetSymbolAddress((void**)&qkvh, g_qkv_hi);
    cudaGetSymbolAddress((void**)&qkvl, g_qkv_lo);
    cudaGetSymbolAddress((void**)&xh,   g_x_hi);
    cudaGetSymbolAddress((void**)&xl,   g_x_lo);
    cudaGetSymbolAddress((void**)&atth, g_att_hi);
    cudaGetSymbolAddress((void**)&attl, g_att_lo);
    cudaGetSymbolAddress((void**)&wth,  g_wt_hi);
    cudaGetSymbolAddress((void**)&wtl,  g_wt_lo);
    cudaGetSymbolAddress((void**)&woth, g_wot_hi);
    cudaGetSymbolAddress((void**)&wotl, g_wot_lo);
    cudaGetSymbolAddress((void**)&vth,  g_vt_hi);
    cudaGetSymbolAddress((void**)&vtl,  g_vt_lo);
    cudaGetSymbolAddress((void**)&lg,   g_l);

    cudaFuncSetAttribute(k_gemm_bf,  cudaFuncAttributeMaxDynamicSharedMemorySize, GSM);
    cudaFuncSetAttribute(k_oproj_ws, cudaFuncAttributeMaxDynamicSharedMemorySize, GSM);
    cudaFuncSetAttribute(k_attn,     cudaFuncAttributeMaxDynamicSharedMemorySize, ASM);

    // prepasses
    k_conv_w<<<dim3(D3 / 32, Dd / 32), 256>>>(Wqkv, wth, wtl, Dd, D3);
    k_conv_w<<<dim3(Dd / 32, Dd / 32), 256>>>(Wo, woth, wotl, Dd, Dd);
    k_conv_x<<<(NT * Dd / 4 + 255) / 256, 256>>>(x, xh, xl, NT * Dd / 4);

    // 1) QKV projection -> hi/lo bf16
    k_gemm_bf<<<dim3(D3 / 128, NT / 128), 256, GSM>>>(xh, xl, wth, wtl, qkvh, qkvl, Dd, D3);

    // 2) V transpose
    k_conv_vt<<<dim3(Tt / 32, 2, BHn), 256>>>(qkvh, qkvl, vth, vtl);

    // 3) fused attention (single pass; W unnormalized, l exported)
    k_attn<<<dim3(16, BHn), 256, ASM>>>(qkvh, qkvl, vth, vtl, wts, lg, atth, attl);

    // 4) fused O projection + fine-grained W normalization
    k_oproj_ws<<<2304, 256, GSM>>>(atth, attl, woth, wotl, bo, out, wts, lg);
}

// round 16
// speedup vs baseline: 1.3158x; 1.1392x over previous
#include <cuda_runtime.h>
#include <cuda_bf16.h>
#include <cstdint>
#include <math.h>

#define Tt 2048
#define Dd 1024
#define Hh 16
#define D3 3072
#define NT 4096      // B*T
#define BHn 32       // B*H

typedef __nv_bfloat16 bf16;

// ---------------- scratch ----------------
__device__ bf16 g_qkv_hi[(size_t)NT * D3];
__device__ bf16 g_qkv_lo[(size_t)NT * D3];
__device__ bf16 g_x_hi[(size_t)NT * Dd];
__device__ bf16 g_x_lo[(size_t)NT * Dd];
__device__ bf16 g_att_hi[(size_t)NT * Dd];
__device__ bf16 g_att_lo[(size_t)NT * Dd];
__device__ bf16 g_wt_hi[(size_t)D3 * Dd];
__device__ bf16 g_wt_lo[(size_t)D3 * Dd];
__device__ bf16 g_wot_hi[(size_t)Dd * Dd];
__device__ bf16 g_wot_lo[(size_t)Dd * Dd];
__device__ bf16 g_vt_hi[(size_t)BHn * 64 * Tt];
__device__ bf16 g_vt_lo[(size_t)BHn * 64 * Tt];
__device__ float g_l[(size_t)BHn * Tt];     // row sums (unnormalized)

// ---------------- helpers ----------------
__device__ __forceinline__ uint32_t smem_u32(const void* p) {
    uint32_t a;
    asm("{ .reg .u64 t; cvta.to.shared.u64 t, %1; cvt.u32.u64 %0, t; }" : "=r"(a) : "l"(p));
    return a;
}

#define LDSM_X4(r0, r1, r2, r3, a) \
    asm volatile("ldmatrix.sync.aligned.m8n8.x4.shared.b16 {%0,%1,%2,%3}, [%4];" \
                 : "=r"(r0), "=r"(r1), "=r"(r2), "=r"(r3) : "r"(a))

#define MMA16816(c, a, b) \
    asm volatile("mma.sync.aligned.m16n8k16.row.col.f32.bf16.bf16.f32 " \
                 "{%0,%1,%2,%3}, {%4,%5,%6,%7}, {%8,%9}, {%0,%1,%2,%3};" \
                 : "+f"((c)[0]), "+f"((c)[1]), "+f"((c)[2]), "+f"((c)[3]) \
                 : "r"((a)[0]), "r"((a)[1]), "r"((a)[2]), "r"((a)[3]), \
                   "r"((b)[0]), "r"((b)[1]))

#define CP16(dst, src) \
    asm volatile("cp.async.cg.shared.global [%0], [%1], 16;" :: "r"(dst), "l"(src) : "memory")
#define CPCOMMIT() asm volatile("cp.async.commit_group;" ::: "memory")
#define CPWAIT2()  asm volatile("cp.async.wait_group 2;" ::: "memory")
#define CPWAIT1()  asm volatile("cp.async.wait_group 1;" ::: "memory")
#define CPWAIT0()  asm volatile("cp.async.wait_group 0;" ::: "memory")

__device__ __forceinline__ uint64_t pack4(bf16 a, bf16 b, bf16 c, bf16 d) {
    __nv_bfloat162 p0(a, b), p1(c, d);
    uint32_t u0 = *(uint32_t*)&p0, u1 = *(uint32_t*)&p1;
    return ((uint64_t)u1 << 32) | u0;
}

__device__ __forceinline__ void st_split2(bf16* __restrict__ H, bf16* __restrict__ L,
                                          size_t off, float a, float b) {
    bf16 ha = __float2bfloat16(a), hb = __float2bfloat16(b);
    *(__nv_bfloat162*)(H + off) = __nv_bfloat162(ha, hb);
    *(__nv_bfloat162*)(L + off) =
        __nv_bfloat162(__float2bfloat16(a - __bfloat162float(ha)),
                       __float2bfloat16(b - __bfloat162float(hb)));
}

// split a float pair into packed bf16 hi + lo u32 regs
__device__ __forceinline__ void split2r(float a, float b, uint32_t& h, uint32_t& l) {
    bf16 ha = __float2bfloat16(a), hb = __float2bfloat16(b);
    __nv_bfloat162 H(ha, hb);
    h = *(uint32_t*)&H;
    __nv_bfloat162 L(__float2bfloat16(a - __bfloat162float(ha)),
                     __float2bfloat16(b - __bfloat162float(hb)));
    l = *(uint32_t*)&L;
}

// async-copy a rows x 64 bf16 tile into padded smem (144B rows)
__device__ __forceinline__ void cpa_tile(uint32_t s_dst, const bf16* __restrict__ src,
                                         int stride, int rows) {
    for (int e = threadIdx.x; e < rows * 8; e += 256) {
        int r = e >> 3, c = e & 7;
        CP16(s_dst + (uint32_t)(r * 144 + c * 16), src + (size_t)r * stride + c * 8);
    }
}

// async-copy a 128 x 32 bf16 tile into padded smem (80B rows)
__device__ __forceinline__ void cpa_tile32(uint32_t s_dst, const bf16* __restrict__ src,
                                           int stride) {
    for (int e = threadIdx.x; e < 128 * 4; e += 256) {
        int r = e >> 2, c = e & 3;
        CP16(s_dst + (uint32_t)(r * 80 + c * 16), src + (size_t)r * stride + c * 8);
    }
}

// generic pass; RS = smem row stride bytes
template<int MI, int NI, int NKB, int RS>
__device__ __forceinline__ void mma_pass(float (*acc)[NI][4], uint32_t sA, uint32_t sB,
                                         int lane, int m0, int n0) {
    #pragma unroll
    for (int kb = 0; kb < NKB; kb++) {
        uint32_t a[MI][4];
        #pragma unroll
        for (int mi = 0; mi < MI; mi++) {
            uint32_t ad = sA + (uint32_t)((m0 + mi * 16 + (lane & 15)) * RS
                                          + kb * 32 + ((lane >> 4) << 4));
            LDSM_X4(a[mi][0], a[mi][1], a[mi][2], a[mi][3], ad);
        }
        uint32_t b[NI][2];
        #pragma unroll
        for (int nb = 0; nb < NI / 2; nb++) {
            uint32_t ad = sB + (uint32_t)((n0 + nb * 16 + ((lane >> 4) << 3) + (lane & 7)) * RS
                                          + kb * 32 + (((lane >> 3) & 1) << 4));
            uint32_t r0, r1, r2, r3;
            LDSM_X4(r0, r1, r2, r3, ad);
            b[2 * nb][0] = r0; b[2 * nb][1] = r1;
            b[2 * nb + 1][0] = r2; b[2 * nb + 1][1] = r3;
        }
        #pragma unroll
        for (int mi = 0; mi < MI; mi++)
            #pragma unroll
            for (int ni = 0; ni < NI; ni++)
                MMA16816(acc[mi][ni], a[mi], b[ni]);
    }
}

// fused hi/lo pass: load Ah/Al/Bh/Bl fragments once, 3 MMAs per (mi,ni)
template<int MI, int NI, int NKB, int RS>
__device__ __forceinline__ void mma_pass3(float (*acc)[NI][4],
                                          uint32_t sAh, uint32_t sAl,
                                          uint32_t sBh, uint32_t sBl,
                                          int lane, int m0, int n0) {
    #pragma unroll
    for (int kb = 0; kb < NKB; kb++) {
        uint32_t ah[MI][4], al[MI][4];
        #pragma unroll
        for (int mi = 0; mi < MI; mi++) {
            uint32_t off = (uint32_t)((m0 + mi * 16 + (lane & 15)) * RS
                                      + kb * 32 + ((lane >> 4) << 4));
            LDSM_X4(ah[mi][0], ah[mi][1], ah[mi][2], ah[mi][3], sAh + off);
            LDSM_X4(al[mi][0], al[mi][1], al[mi][2], al[mi][3], sAl + off);
        }
        uint32_t bh[NI][2], bl[NI][2];
        #pragma unroll
        for (int nb = 0; nb < NI / 2; nb++) {
            uint32_t off = (uint32_t)((n0 + nb * 16 + ((lane >> 4) << 3) + (lane & 7)) * RS
                                      + kb * 32 + (((lane >> 3) & 1) << 4));
            uint32_t r0, r1, r2, r3;
            LDSM_X4(r0, r1, r2, r3, sBh + off);
            bh[2 * nb][0] = r0; bh[2 * nb][1] = r1;
            bh[2 * nb + 1][0] = r2; bh[2 * nb + 1][1] = r3;
            LDSM_X4(r0, r1, r2, r3, sBl + off);
            bl[2 * nb][0] = r0; bl[2 * nb][1] = r1;
            bl[2 * nb + 1][0] = r2; bl[2 * nb + 1][1] = r3;
        }
        #pragma unroll
        for (int mi = 0; mi < MI; mi++)
            #pragma unroll
            for (int ni = 0; ni < NI; ni++) {
                MMA16816(acc[mi][ni], ah[mi], bh[ni]);
                MMA16816(acc[mi][ni], ah[mi], bl[ni]);
                MMA16816(acc[mi][ni], al[mi], bh[ni]);
            }
    }
}

// PV pass with register A-fragments: 4 k16-chunks, 8 dh n8-tiles, V smem RS=144
__device__ __forceinline__ void pv_pass(float (*accO)[4], const uint32_t (*af)[4],
                                        uint32_t sV, int lane) {
    #pragma unroll
    for (int kb = 0; kb < 4; kb++) {
        uint32_t b[8][2];
        #pragma unroll
        for (int nb = 0; nb < 4; nb++) {
            uint32_t ad = sV + (uint32_t)((nb * 16 + ((lane >> 4) << 3) + (lane & 7)) * 144
                                          + kb * 32 + (((lane >> 3) & 1) << 4));
            uint32_t r0, r1, r2, r3;
            LDSM_X4(r0, r1, r2, r3, ad);
            b[2 * nb][0] = r0; b[2 * nb][1] = r1;
            b[2 * nb + 1][0] = r2; b[2 * nb + 1][1] = r3;
        }
        #pragma unroll
        for (int ni = 0; ni < 8; ni++)
            MMA16816(accO[ni], af[kb], b[ni]);
    }
}

// ---------------- GEMM core (double-buffered cp.async, BK=32, 2 CTAs/SM) ----
#define GSTG 40960
#define GSM  81920

__device__ __forceinline__ void gemm_issue(uint32_t sb, int stage,
                                           const bf16* Ah, const bf16* Al,
                                           const bf16* Bh, const bf16* Bl,
                                           int K, int m0, int n0, int c) {
    uint32_t st = sb + stage * GSTG;
    const size_t ao = (size_t)m0 * K + c * 32, bo = (size_t)n0 * K + c * 32;
    cpa_tile32(st,         Ah + ao, K);
    cpa_tile32(st + 10240, Al + ao, K);
    cpa_tile32(st + 20480, Bh + bo, K);
    cpa_tile32(st + 30720, Bl + bo, K);
    CPCOMMIT();
}

__device__ __forceinline__ void gemm_core(float (*acc)[4][4],
                                          const bf16* Ah, const bf16* Al,
                                          const bf16* Bh, const bf16* Bl,
                                          int K, int m0, int n0,
                                          uint32_t sb, int lane, int wm, int wn) {
    const int nc = K / 32;
    gemm_issue(sb, 0, Ah, Al, Bh, Bl, K, m0, n0, 0);
    for (int c = 0; c < nc; c++) {
        if (c + 1 < nc) {
            gemm_issue(sb, (c + 1) & 1, Ah, Al, Bh, Bl, K, m0, n0, c + 1);
            CPWAIT1();
        } else CPWAIT0();
        __syncthreads();
        uint32_t st = sb + (c & 1) * GSTG;
        mma_pass3<4, 4, 2, 80>(acc, st, st + 10240, st + 20480, st + 30720, lane, wm, wn);
        __syncthreads();
    }
}

__global__ __launch_bounds__(256, 2) void k_gemm_bf(const bf16* __restrict__ Ah,
                                                    const bf16* __restrict__ Al,
                                                    const bf16* __restrict__ Bh,
                                                    const bf16* __restrict__ Bl,
                                                    bf16* __restrict__ Ch,
                                                    bf16* __restrict__ Cl, int K, int N) {
    extern __shared__ char smem[];
    uint32_t sb = smem_u32(smem);
    const int tid = threadIdx.x, lane = tid & 31, wid = tid >> 5;
    const int m0 = blockIdx.y * 128, n0 = blockIdx.x * 128;
    const int wm = (wid >> 2) * 64, wn = (wid & 3) * 32;

    float acc[4][4][4];
    #pragma unroll
    for (int i = 0; i < 4; i++)
        #pragma unroll
        for (int j = 0; j < 4; j++)
            #pragma unroll
            for (int q = 0; q < 4; q++) acc[i][j][q] = 0.f;

    gemm_core(acc, Ah, Al, Bh, Bl, K, m0, n0, sb, lane, wm, wn);

    #pragma unroll
    for (int mi = 0; mi < 4; mi++) {
        int r = m0 + wm + mi * 16 + (lane >> 2);
        #pragma unroll
        for (int ni = 0; ni < 4; ni++) {
            int c = n0 + wn + ni * 8 + (lane & 3) * 2;
            st_split2(Ch, Cl, (size_t)r * N + c, acc[mi][ni][0], acc[mi][ni][1]);
            st_split2(Ch, Cl, (size_t)(r + 8) * N + c, acc[mi][ni][2], acc[mi][ni][3]);
        }
    }
}

__global__ __launch_bounds__(256, 2) void k_gemm_f32(const bf16* __restrict__ Ah,
                                                     const bf16* __restrict__ Al,
                                                     const bf16* __restrict__ Bh,
                                                     const bf16* __restrict__ Bl,
                                                     const float* __restrict__ bias,
                                                     float* __restrict__ C, int K, int N) {
    extern __shared__ char smem[];
    uint32_t sb = smem_u32(smem);
    const int tid = threadIdx.x, lane = tid & 31, wid = tid >> 5;
    const int m0 = blockIdx.y * 128, n0 = blockIdx.x * 128;
    const int wm = (wid >> 2) * 64, wn = (wid & 3) * 32;

    float acc[4][4][4];
    #pragma unroll
    for (int i = 0; i < 4; i++)
        #pragma unroll
        for (int j = 0; j < 4; j++)
            #pragma unroll
            for (int q = 0; q < 4; q++) acc[i][j][q] = 0.f;

    gemm_core(acc, Ah, Al, Bh, Bl, K, m0, n0, sb, lane, wm, wn);

    #pragma unroll
    for (int mi = 0; mi < 4; mi++) {
        int r = m0 + wm + mi * 16 + (lane >> 2);
        #pragma unroll
        for (int ni = 0; ni < 4; ni++) {
            int c = n0 + wn + ni * 8 + (lane & 3) * 2;
            float bx = bias[c], by = bias[c + 1];
            *(float2*)&C[(size_t)r * N + c] =
                make_float2(acc[mi][ni][0] + bx, acc[mi][ni][1] + by);
            *(float2*)&C[(size_t)(r + 8) * N + c] =
                make_float2(acc[mi][ni][2] + bx, acc[mi][ni][3] + by);
        }
    }
}

// ---------------- fused causal attention (single-pass, deferred normalize) --
#define SQH 0
#define SQL 18432
#define SKB 36864
#define SVB 110592
#define ASM 184320

__global__ __launch_bounds__(256) void k_attn(const bf16* __restrict__ qkvh,
                                              const bf16* __restrict__ qkvl,
                                              const bf16* __restrict__ vth,
                                              const bf16* __restrict__ vtl,
                                              float* __restrict__ wts,
                                              float* __restrict__ lg,
                                              bf16* __restrict__ atth,
                                              bf16* __restrict__ attl) {
    extern __shared__ char smem[];
    uint32_t sb = smem_u32(smem);

    const int tid = threadIdx.x, lane = tid & 31, wid = tid >> 5;
    const int i = 15 - blockIdx.x;            // heavy tiles first
    const int bh = blockIdx.y, b = bh >> 4, h = bh & 15;
    float* wbase = wts + ((size_t)bh * Tt + i * 128) * Tt;

    const bf16* qb_h = qkvh + ((size_t)b * Tt + i * 128) * D3 + h * 64;
    const bf16* qb_l = qkvl + ((size_t)b * Tt + i * 128) * D3 + h * 64;
    const bf16* kbase_h = qkvh + (size_t)b * Tt * D3 + Dd + h * 64;
    const bf16* kbase_l = qkvl + (size_t)b * Tt * D3 + Dd + h * 64;
    const bf16* vb_h = vth + (size_t)bh * 64 * Tt;
    const bf16* vb_l = vtl + (size_t)bh * 64 * Tt;

    const int wm = wid * 16;                  // warp's 16-row strip
    const int g = lane >> 2, qq = lane & 3;
    const int r0 = wm + g;                    // local row (and r0+8)

    // Q (group), K0 (group), V0 (group)
    cpa_tile(sb + SQH, qb_h, D3, 128);
    cpa_tile(sb + SQL, qb_l, D3, 128);
    CPCOMMIT();
    cpa_tile(sb + SKB,         kbase_h, D3, 128);
    cpa_tile(sb + SKB + 18432, kbase_l, D3, 128);
    CPCOMMIT();
    cpa_tile(sb + SVB,         vb_h,      Tt, 64);
    cpa_tile(sb + SVB + 9216,  vb_l,      Tt, 64);
    cpa_tile(sb + SVB + 18432, vb_h + 64, Tt, 64);
    cpa_tile(sb + SVB + 27648, vb_l + 64, Tt, 64);
    CPCOMMIT();

    // overlap: zero causal tail
    {
        int tail0 = (i + 1) * 128;
        int n4 = (Tt - tail0) >> 2;
        for (int e = tid; e < 128 * n4; e += 256) {
            int row = e / n4, c4 = e % n4;
            *(float4*)(wbase + (size_t)row * Tt + tail0 + c4 * 4) =
                make_float4(0.f, 0.f, 0.f, 0.f);
        }
    }

    float l0 = 0.f, l1 = 0.f;
    float accO[8][4];
    #pragma unroll
    for (int ni = 0; ni < 8; ni++)
        #pragma unroll
        for (int q = 0; q < 4; q++) accO[ni][q] = 0.f;

    // ---- single loop: S -> exp -> W + reg-P -> PV ----
    for (int kt = 0; kt <= i; kt++) {
        if (kt < i) {
            uint32_t stk = sb + SKB + ((kt + 1) & 1) * 36864;
            cpa_tile(stk,         kbase_h + (size_t)(kt + 1) * 128 * D3, D3, 128);
            cpa_tile(stk + 18432, kbase_l + (size_t)(kt + 1) * 128 * D3, D3, 128);
            CPCOMMIT();
            uint32_t stv = sb + SVB + ((kt + 1) & 1) * 36864;
            cpa_tile(stv,         vb_h + (kt + 1) * 128,      Tt, 64);
            cpa_tile(stv + 9216,  vb_l + (kt + 1) * 128,      Tt, 64);
            cpa_tile(stv + 18432, vb_h + (kt + 1) * 128 + 64, Tt, 64);
            cpa_tile(stv + 27648, vb_l + (kt + 1) * 128 + 64, Tt, 64);
            CPCOMMIT();
            CPWAIT2();                        // K_kt, V_kt (and older) ready
        } else CPWAIT0();
        __syncthreads();

        uint32_t stK = sb + SKB + (kt & 1) * 36864;
        uint32_t stV = sb + SVB + (kt & 1) * 36864;

        float accS[1][16][4];
        #pragma unroll
        for (int ni = 0; ni < 16; ni++)
            #pragma unroll
            for (int q = 0; q < 4; q++) accS[0][ni][q] = 0.f;
        mma_pass<1, 16, 4, 144>(accS, sb + SQH, stK,         lane, wm, 0);
        mma_pass<1, 16, 4, 144>(accS, sb + SQH, stK + 18432, lane, wm, 0);
        mma_pass<1, 16, 4, 144>(accS, sb + SQL, stK,         lane, wm, 0);

        // exp, unnormalized W write, register P fragments, l accumulation
        uint32_t phi[8][4], plo[8][4];
        #pragma unroll
        for (int ni = 0; ni < 16; ni++) {
            int c = ni * 8 + qq * 2;
            float v0 = accS[0][ni][0] * 0.125f, v1 = accS[0][ni][1] * 0.125f;
            float v2 = accS[0][ni][2] * 0.125f, v3 = accS[0][ni][3] * 0.125f;
            if (kt == i) {
                if (c     > r0)     v0 = -INFINITY;
                if (c + 1 > r0)     v1 = -INFINITY;
                if (c     > r0 + 8) v2 = -INFINITY;
                if (c + 1 > r0 + 8) v3 = -INFINITY;
            }
            float p0 = __expf(v0), p1 = __expf(v1);
            float p2 = __expf(v2), p3 = __expf(v3);
            l0 += p0 + p1;
            l1 += p2 + p3;
            *(float2*)&wbase[(size_t)r0 * Tt + kt * 128 + c] = make_float2(p0, p1);
            *(float2*)&wbase[(size_t)(r0 + 8) * Tt + kt * 128 + c] = make_float2(p2, p3);
            int kb = ni >> 1, hf = (ni & 1) << 1;
            split2r(p0, p1, phi[kb][hf],     plo[kb][hf]);
            split2r(p2, p3, phi[kb][hf + 1], plo[kb][hf + 1]);
        }

        #pragma unroll
        for (int cchunk = 0; cchunk < 2; cchunk++) {
            uint32_t svh = stV + cchunk * 18432;
            pv_pass(accO, phi + 4 * cchunk, svh,        lane);
            pv_pass(accO, phi + 4 * cchunk, svh + 9216, lane);
            pv_pass(accO, plo + 4 * cchunk, svh,        lane);
        }
        __syncthreads();   // protect stage reuse
    }

    // finish row sums within lane-quads, export l, normalize O
    l0 += __shfl_xor_sync(0xffffffffu, l0, 1);
    l0 += __shfl_xor_sync(0xffffffffu, l0, 2);
    l1 += __shfl_xor_sync(0xffffffffu, l1, 1);
    l1 += __shfl_xor_sync(0xffffffffu, l1, 2);
    if (qq == 0) {
        lg[(size_t)bh * Tt + i * 128 + r0]     = l0;
        lg[(size_t)bh * Tt + i * 128 + r0 + 8] = l1;
    }
    const float il0 = 1.f / l0, il1 = 1.f / l1;

    {
        int q0 = i * 128 + r0;
        size_t base0 = ((size_t)b * Tt + q0) * Dd + h * 64;
        size_t base8 = base0 + (size_t)8 * Dd;
        #pragma unroll
        for (int ni = 0; ni < 8; ni++) {
            int c = ni * 8 + qq * 2;
            st_split2(atth, attl, base0 + c, accO[ni][0] * il0, accO[ni][1] * il0);
            st_split2(atth, attl, base8 + c, accO[ni][2] * il1, accO[ni][3] * il1);
        }
    }
}

// streaming W normalization: row *= 1/l over the causal tile prefix
__global__ __launch_bounds__(128) void k_wscale(float* __restrict__ w,
                                                const float* __restrict__ lg) {
    const int row = blockIdx.x;
    const float il = 1.f / lg[row];
    const int r = row & (Tt - 1);
    const int n4 = ((r >> 7) + 1) * 32;       // float4 count (tile-aligned prefix)
    float4* p = (float4*)(w + (size_t)row * Tt);
    for (int e = threadIdx.x; e < n4; e += 128) {
        float4 v = p[e];
        v.x *= il; v.y *= il; v.z *= il; v.w *= il;
        p[e] = v;
    }
}

// ---------------- prepasses ----------------
__global__ __launch_bounds__(256) void k_conv_x(const float* __restrict__ X,
                                                bf16* __restrict__ hi, bf16* __restrict__ lo,
                                                int n4) {
    int idx = blockIdx.x * 256 + threadIdx.x;
    if (idx >= n4) return;
    float4 v = ((const float4*)X)[idx];
    bf16 h0 = __float2bfloat16(v.x), h1 = __float2bfloat16(v.y);
    bf16 h2 = __float2bfloat16(v.z), h3 = __float2bfloat16(v.w);
    ((uint64_t*)hi)[idx] = pack4(h0, h1, h2, h3);
    ((uint64_t*)lo)[idx] = pack4(__float2bfloat16(v.x - __bfloat162float(h0)),
                                 __float2bfloat16(v.y - __bfloat162float(h1)),
                                 __float2bfloat16(v.z - __bfloat162float(h2)),
                                 __float2bfloat16(v.w - __bfloat162float(h3)));
}

__global__ __launch_bounds__(256) void k_conv_w(const float* __restrict__ W,
                                                bf16* __restrict__ hi, bf16* __restrict__ lo,
                                                int K, int N) {
    __shared__ float tile[32][33];
    const int n0 = blockIdx.x * 32, k0 = blockIdx.y * 32;
    const int tx = threadIdx.x & 31, ty = threadIdx.x >> 5;
    for (int r = ty; r < 32; r += 8) tile[r][tx] = W[(size_t)(k0 + r) * N + n0 + tx];
    __syncthreads();
    for (int r = ty; r < 32; r += 8) {
        float v = tile[tx][r];
        size_t o = (size_t)(n0 + r) * K + k0 + tx;
        bf16 h = __float2bfloat16(v);
        hi[o] = h;
        lo[o] = __float2bfloat16(v - __bfloat162float(h));
    }
}

__global__ __launch_bounds__(256) void k_conv_vt(const bf16* __restrict__ qh,
                                                 const bf16* __restrict__ ql,
                                                 bf16* __restrict__ hi, bf16* __restrict__ lo) {
    __shared__ bf16 th[32][33], tl[32][33];
    const int bh = blockIdx.z, b = bh >> 4, h = bh & 15;
    const int t0 = blockIdx.x * 32, d0 = blockIdx.y * 32;
    const int tx = threadIdx.x & 31, ty = threadIdx.x >> 5;
    const size_t sbase = ((size_t)b * Tt + t0) * D3 + 2 * Dd + h * 64 + d0;
    for (int r = ty; r < 32; r += 8) {
        th[r][tx] = qh[sbase + (size_t)r * D3 + tx];
        tl[r][tx] = ql[sbase + (size_t)r * D3 + tx];
    }
    __syncthreads();
    bf16* oh = hi + (size_t)bh * 64 * Tt;
    bf16* ol = lo + (size_t)bh * 64 * Tt;
    for (int r = ty; r < 32; r += 8) {
        size_t o = (size_t)(d0 + r) * Tt + t0 + tx;
        oh[o] = th[tx][r];
        ol[o] = tl[tx][r];
    }
}

// ---------------------------------------------------------------------------
extern "C" void kernel_launch(void* const* d_in, const int* in_sizes, int n_in,
                              void* d_out, int out_size) {
    const float* x    = (const float*)d_in[0];
    const float* Wqkv = (const float*)d_in[2];
    const float* Wo   = (const float*)d_in[3];
    const float* bo   = (const float*)d_in[4];

    float* out = (float*)d_out;                 // [B,T,D]
    float* wts = out + (size_t)NT * Dd;         // [B,H,T,T]

    bf16 *qkvh, *qkvl, *xh, *xl, *atth, *attl;
    bf16 *wth, *wtl, *woth, *wotl, *vth, *vtl;
    float* lg;
    cudaGetSymbolAddress((void**)&qkvh, g_qkv_hi);
    cudaGetSymbolAddress((void**)&qkvl, g_qkv_lo);
    cudaGetSymbolAddress((void**)&xh,   g_x_hi);
    cudaGetSymbolAddress((void**)&xl,   g_x_lo);
    cudaGetSymbolAddress((void**)&atth, g_att_hi);
    cudaGetSymbolAddress((void**)&attl, g_att_lo);
    cudaGetSymbolAddress((void**)&wth,  g_wt_hi);
    cudaGetSymbolAddress((void**)&wtl,  g_wt_lo);
    cudaGetSymbolAddress((void**)&woth, g_wot_hi);
    cudaGetSymbolAddress((void**)&wotl, g_wot_lo);
    cudaGetSymbolAddress((void**)&vth,  g_vt_hi);
    cudaGetSymbolAddress((void**)&vtl,  g_vt_lo);
    cudaGetSymbolAddress((void**)&lg,   g_l);

    cudaFuncSetAttribute(k_gemm_bf,  cudaFuncAttributeMaxDynamicSharedMemorySize, GSM);
    cudaFuncSetAttribute(k_gemm_f32, cudaFuncAttributeMaxDynamicSharedMemorySize, GSM);
    cudaFuncSetAttribute(k_attn,     cudaFuncAttributeMaxDynamicSharedMemorySize, ASM);

    // prepasses
    k_conv_w<<<dim3(D3 / 32, Dd / 32), 256>>>(Wqkv, wth, wtl, Dd, D3);
    k_conv_w<<<dim3(Dd / 32, Dd / 32), 256>>>(Wo, woth, wotl, Dd, Dd);
    k_conv_x<<<(NT * Dd / 4 + 255) / 256, 256>>>(x, xh, xl, NT * Dd / 4);

    // 1) QKV projection -> hi/lo bf16
    k_gemm_bf<<<dim3(D3 / 128, NT / 128), 256, GSM>>>(xh, xl, wth, wtl, qkvh, qkvl, Dd, D3);

    // 2) V transpose
    k_conv_vt<<<dim3(Tt / 32, 2, BHn), 256>>>(qkvh, qkvl, vth, vtl);

    // 3) fused attention (single pass; W unnormalized, l exported)
    k_attn<<<dim3(16, BHn), 256, ASM>>>(qkvh, qkvl, vth, vtl, wts, lg, atth, attl);

    // 4) + 5) run O-projection and W-normalization on PARALLEL graph branches
    cudaStream_t s2;
    cudaEvent_t e_fork, e_join;
    bool forked = (cudaStreamCreateWithFlags(&s2, cudaStreamNonBlocking) == cudaSuccess) &&
                  (cudaEventCreateWithFlags(&e_fork, cudaEventDisableTiming) == cudaSuccess) &&
                  (cudaEventCreateWithFlags(&e_join, cudaEventDisableTiming) == cudaSuccess);
    if (forked) {
        cudaEventRecord(e_fork, 0);
        cudaStreamWaitEvent(s2, e_fork, 0);
        k_wscale<<<BHn * Tt, 128, 0, s2>>>(wts, lg);
        cudaEventRecord(e_join, s2);
        k_gemm_f32<<<dim3(Dd / 128, NT / 128), 256, GSM>>>(atth, attl, woth, wotl, bo, out, Dd, Dd);
        cudaStreamWaitEvent(0, e_join, 0);
    } else {
        // fallback: serial
        k_gemm_f32<<<dim3(Dd / 128, NT / 128), 256, GSM>>>(atth, attl, woth, wotl, bo, out, Dd, Dd);
        k_wscale<<<BHn * Tt, 128>>>(wts, lg);
    }
}

// round 17
// speedup vs baseline: 1.3589x; 1.0328x over previous
#include <cuda_runtime.h>
#include <cuda_bf16.h>
#include <cstdint>
#include <math.h>

#define Tt 2048
#define Dd 1024
#define Hh 16
#define D3 3072
#define NT 4096      // B*T
#define BHn 32       // B*H

typedef __nv_bfloat16 bf16;

// ---------------- scratch ----------------
__device__ bf16 g_qkv_hi[(size_t)NT * D3];
__device__ bf16 g_qkv_lo[(size_t)NT * D3];
__device__ bf16 g_x_hi[(size_t)NT * Dd];
__device__ bf16 g_x_lo[(size_t)NT * Dd];
__device__ bf16 g_att_hi[(size_t)NT * Dd];
__device__ bf16 g_att_lo[(size_t)NT * Dd];
__device__ bf16 g_wt_hi[(size_t)D3 * Dd];
__device__ bf16 g_wt_lo[(size_t)D3 * Dd];
__device__ bf16 g_wot_hi[(size_t)Dd * Dd];
__device__ bf16 g_wot_lo[(size_t)Dd * Dd];
__device__ bf16 g_vt_hi[(size_t)BHn * 64 * Tt];
__device__ bf16 g_vt_lo[(size_t)BHn * 64 * Tt];
__device__ float g_l[(size_t)BHn * Tt];     // row sums (unnormalized)

// ---------------- helpers ----------------
__device__ __forceinline__ uint32_t smem_u32(const void* p) {
    uint32_t a;
    asm("{ .reg .u64 t; cvta.to.shared.u64 t, %1; cvt.u32.u64 %0, t; }" : "=r"(a) : "l"(p));
    return a;
}

#define LDSM_X4(r0, r1, r2, r3, a) \
    asm volatile("ldmatrix.sync.aligned.m8n8.x4.shared.b16 {%0,%1,%2,%3}, [%4];" \
                 : "=r"(r0), "=r"(r1), "=r"(r2), "=r"(r3) : "r"(a))

#define MMA16816(c, a, b) \
    asm volatile("mma.sync.aligned.m16n8k16.row.col.f32.bf16.bf16.f32 " \
                 "{%0,%1,%2,%3}, {%4,%5,%6,%7}, {%8,%9}, {%0,%1,%2,%3};" \
                 : "+f"((c)[0]), "+f"((c)[1]), "+f"((c)[2]), "+f"((c)[3]) \
                 : "r"((a)[0]), "r"((a)[1]), "r"((a)[2]), "r"((a)[3]), \
                   "r"((b)[0]), "r"((b)[1]))

#define CP16(dst, src) \
    asm volatile("cp.async.cg.shared.global [%0], [%1], 16;" :: "r"(dst), "l"(src) : "memory")
#define CPCOMMIT() asm volatile("cp.async.commit_group;" ::: "memory")
#define CPWAIT2()  asm volatile("cp.async.wait_group 2;" ::: "memory")
#define CPWAIT1()  asm volatile("cp.async.wait_group 1;" ::: "memory")
#define CPWAIT0()  asm volatile("cp.async.wait_group 0;" ::: "memory")

__device__ __forceinline__ uint64_t pack4(bf16 a, bf16 b, bf16 c, bf16 d) {
    __nv_bfloat162 p0(a, b), p1(c, d);
    uint32_t u0 = *(uint32_t*)&p0, u1 = *(uint32_t*)&p1;
    return ((uint64_t)u1 << 32) | u0;
}

__device__ __forceinline__ void st_split2(bf16* __restrict__ H, bf16* __restrict__ L,
                                          size_t off, float a, float b) {
    bf16 ha = __float2bfloat16(a), hb = __float2bfloat16(b);
    *(__nv_bfloat162*)(H + off) = __nv_bfloat162(ha, hb);
    *(__nv_bfloat162*)(L + off) =
        __nv_bfloat162(__float2bfloat16(a - __bfloat162float(ha)),
                       __float2bfloat16(b - __bfloat162float(hb)));
}

// split a float pair into packed bf16 hi + lo u32 regs
__device__ __forceinline__ void split2r(float a, float b, uint32_t& h, uint32_t& l) {
    bf16 ha = __float2bfloat16(a), hb = __float2bfloat16(b);
    __nv_bfloat162 H(ha, hb);
    h = *(uint32_t*)&H;
    __nv_bfloat162 L(__float2bfloat16(a - __bfloat162float(ha)),
                     __float2bfloat16(b - __bfloat162float(hb)));
    l = *(uint32_t*)&L;
}

// async-copy a rows x 64 bf16 tile into padded smem (144B rows)
__device__ __forceinline__ void cpa_tile(uint32_t s_dst, const bf16* __restrict__ src,
                                         int stride, int rows) {
    for (int e = threadIdx.x; e < rows * 8; e += 256) {
        int r = e >> 3, c = e & 7;
        CP16(s_dst + (uint32_t)(r * 144 + c * 16), src + (size_t)r * stride + c * 8);
    }
}

// async-copy a 128 x 32 bf16 tile into padded smem (80B rows)
__device__ __forceinline__ void cpa_tile32(uint32_t s_dst, const bf16* __restrict__ src,
                                           int stride) {
    for (int e = threadIdx.x; e < 128 * 4; e += 256) {
        int r = e >> 2, c = e & 3;
        CP16(s_dst + (uint32_t)(r * 80 + c * 16), src + (size_t)r * stride + c * 8);
    }
}

// generic pass; RS = smem row stride bytes
template<int MI, int NI, int NKB, int RS>
__device__ __forceinline__ void mma_pass(float (*acc)[NI][4], uint32_t sA, uint32_t sB,
                                         int lane, int m0, int n0) {
    #pragma unroll
    for (int kb = 0; kb < NKB; kb++) {
        uint32_t a[MI][4];
        #pragma unroll
        for (int mi = 0; mi < MI; mi++) {
            uint32_t ad = sA + (uint32_t)((m0 + mi * 16 + (lane & 15)) * RS
                                          + kb * 32 + ((lane >> 4) << 4));
            LDSM_X4(a[mi][0], a[mi][1], a[mi][2], a[mi][3], ad);
        }
        uint32_t b[NI][2];
        #pragma unroll
        for (int nb = 0; nb < NI / 2; nb++) {
            uint32_t ad = sB + (uint32_t)((n0 + nb * 16 + ((lane >> 4) << 3) + (lane & 7)) * RS
                                          + kb * 32 + (((lane >> 3) & 1) << 4));
            uint32_t r0, r1, r2, r3;
            LDSM_X4(r0, r1, r2, r3, ad);
            b[2 * nb][0] = r0; b[2 * nb][1] = r1;
            b[2 * nb + 1][0] = r2; b[2 * nb + 1][1] = r3;
        }
        #pragma unroll
        for (int mi = 0; mi < MI; mi++)
            #pragma unroll
            for (int ni = 0; ni < NI; ni++)
                MMA16816(acc[mi][ni], a[mi], b[ni]);
    }
}

// fused hi/lo pass: load Ah/Al/Bh/Bl fragments once, 3 MMAs per (mi,ni)
template<int MI, int NI, int NKB, int RS>
__device__ __forceinline__ void mma_pass3(float (*acc)[NI][4],
                                          uint32_t sAh, uint32_t sAl,
                                          uint32_t sBh, uint32_t sBl,
                                          int lane, int m0, int n0) {
    #pragma unroll
    for (int kb = 0; kb < NKB; kb++) {
        uint32_t ah[MI][4], al[MI][4];
        #pragma unroll
        for (int mi = 0; mi < MI; mi++) {
            uint32_t off = (uint32_t)((m0 + mi * 16 + (lane & 15)) * RS
                                      + kb * 32 + ((lane >> 4) << 4));
            LDSM_X4(ah[mi][0], ah[mi][1], ah[mi][2], ah[mi][3], sAh + off);
            LDSM_X4(al[mi][0], al[mi][1], al[mi][2], al[mi][3], sAl + off);
        }
        uint32_t bh[NI][2], bl[NI][2];
        #pragma unroll
        for (int nb = 0; nb < NI / 2; nb++) {
            uint32_t off = (uint32_t)((n0 + nb * 16 + ((lane >> 4) << 3) + (lane & 7)) * RS
                                      + kb * 32 + (((lane >> 3) & 1) << 4));
            uint32_t r0, r1, r2, r3;
            LDSM_X4(r0, r1, r2, r3, sBh + off);
            bh[2 * nb][0] = r0; bh[2 * nb][1] = r1;
            bh[2 * nb + 1][0] = r2; bh[2 * nb + 1][1] = r3;
            LDSM_X4(r0, r1, r2, r3, sBl + off);
            bl[2 * nb][0] = r0; bl[2 * nb][1] = r1;
            bl[2 * nb + 1][0] = r2; bl[2 * nb + 1][1] = r3;
        }
        #pragma unroll
        for (int mi = 0; mi < MI; mi++)
            #pragma unroll
            for (int ni = 0; ni < NI; ni++) {
                MMA16816(acc[mi][ni], ah[mi], bh[ni]);
                MMA16816(acc[mi][ni], ah[mi], bl[ni]);
                MMA16816(acc[mi][ni], al[mi], bh[ni]);
            }
    }
}

// PV pass with register A-fragments: 4 k16-chunks, 8 dh n8-tiles, V smem RS=144
__device__ __forceinline__ void pv_pass(float (*accO)[4], const uint32_t (*af)[4],
                                        uint32_t sV, int lane) {
    #pragma unroll
    for (int kb = 0; kb < 4; kb++) {
        uint32_t b[8][2];
        #pragma unroll
        for (int nb = 0; nb < 4; nb++) {
            uint32_t ad = sV + (uint32_t)((nb * 16 + ((lane >> 4) << 3) + (lane & 7)) * 144
                                          + kb * 32 + (((lane >> 3) & 1) << 4));
            uint32_t r0, r1, r2, r3;
            LDSM_X4(r0, r1, r2, r3, ad);
            b[2 * nb][0] = r0; b[2 * nb][1] = r1;
            b[2 * nb + 1][0] = r2; b[2 * nb + 1][1] = r3;
        }
        #pragma unroll
        for (int ni = 0; ni < 8; ni++)
            MMA16816(accO[ni], af[kb], b[ni]);
    }
}

// ---------------- GEMM core (double-buffered cp.async, BK=32, 2 CTAs/SM) ----
#define GSTG 40960
#define GSM  81920

__device__ __forceinline__ void gemm_issue(uint32_t sb, int stage,
                                           const bf16* Ah, const bf16* Al,
                                           const bf16* Bh, const bf16* Bl,
                                           int K, int m0, int n0, int c) {
    uint32_t st = sb + stage * GSTG;
    const size_t ao = (size_t)m0 * K + c * 32, bo = (size_t)n0 * K + c * 32;
    cpa_tile32(st,         Ah + ao, K);
    cpa_tile32(st + 10240, Al + ao, K);
    cpa_tile32(st + 20480, Bh + bo, K);
    cpa_tile32(st + 30720, Bl + bo, K);
    CPCOMMIT();
}

__device__ __forceinline__ void gemm_core(float (*acc)[4][4],
                                          const bf16* Ah, const bf16* Al,
                                          const bf16* Bh, const bf16* Bl,
                                          int K, int m0, int n0,
                                          uint32_t sb, int lane, int wm, int wn) {
    const int nc = K / 32;
    gemm_issue(sb, 0, Ah, Al, Bh, Bl, K, m0, n0, 0);
    for (int c = 0; c < nc; c++) {
        if (c + 1 < nc) {
            gemm_issue(sb, (c + 1) & 1, Ah, Al, Bh, Bl, K, m0, n0, c + 1);
            CPWAIT1();
        } else CPWAIT0();
        __syncthreads();
        uint32_t st = sb + (c & 1) * GSTG;
        mma_pass3<4, 4, 2, 80>(acc, st, st + 10240, st + 20480, st + 30720, lane, wm, wn);
        __syncthreads();
    }
}

__global__ __launch_bounds__(256, 2) void k_gemm_bf(const bf16* __restrict__ Ah,
                                                    const bf16* __restrict__ Al,
                                                    const bf16* __restrict__ Bh,
                                                    const bf16* __restrict__ Bl,
                                                    bf16* __restrict__ Ch,
                                                    bf16* __restrict__ Cl, int K, int N) {
    extern __shared__ char smem[];
    uint32_t sb = smem_u32(smem);
    const int tid = threadIdx.x, lane = tid & 31, wid = tid >> 5;
    const int m0 = blockIdx.y * 128, n0 = blockIdx.x * 128;
    const int wm = (wid >> 2) * 64, wn = (wid & 3) * 32;

    float acc[4][4][4];
    #pragma unroll
    for (int i = 0; i < 4; i++)
        #pragma unroll
        for (int j = 0; j < 4; j++)
            #pragma unroll
            for (int q = 0; q < 4; q++) acc[i][j][q] = 0.f;

    gemm_core(acc, Ah, Al, Bh, Bl, K, m0, n0, sb, lane, wm, wn);

    #pragma unroll
    for (int mi = 0; mi < 4; mi++) {
        int r = m0 + wm + mi * 16 + (lane >> 2);
        #pragma unroll
        for (int ni = 0; ni < 4; ni++) {
            int c = n0 + wn + ni * 8 + (lane & 3) * 2;
            st_split2(Ch, Cl, (size_t)r * N + c, acc[mi][ni][0], acc[mi][ni][1]);
            st_split2(Ch, Cl, (size_t)(r + 8) * N + c, acc[mi][ni][2], acc[mi][ni][3]);
        }
    }
}

__global__ __launch_bounds__(256, 2) void k_gemm_f32(const bf16* __restrict__ Ah,
                                                     const bf16* __restrict__ Al,
                                                     const bf16* __restrict__ Bh,
                                                     const bf16* __restrict__ Bl,
                                                     const float* __restrict__ bias,
                                                     float* __restrict__ C, int K, int N) {
    extern __shared__ char smem[];
    uint32_t sb = smem_u32(smem);
    const int tid = threadIdx.x, lane = tid & 31, wid = tid >> 5;
    const int m0 = blockIdx.y * 128, n0 = blockIdx.x * 128;
    const int wm = (wid >> 2) * 64, wn = (wid & 3) * 32;

    float acc[4][4][4];
    #pragma unroll
    for (int i = 0; i < 4; i++)
        #pragma unroll
        for (int j = 0; j < 4; j++)
            #pragma unroll
            for (int q = 0; q < 4; q++) acc[i][j][q] = 0.f;

    gemm_core(acc, Ah, Al, Bh, Bl, K, m0, n0, sb, lane, wm, wn);

    #pragma unroll
    for (int mi = 0; mi < 4; mi++) {
        int r = m0 + wm + mi * 16 + (lane >> 2);
        #pragma unroll
        for (int ni = 0; ni < 4; ni++) {
            int c = n0 + wn + ni * 8 + (lane & 3) * 2;
            float bx = bias[c], by = bias[c + 1];
            *(float2*)&C[(size_t)r * N + c] =
                make_float2(acc[mi][ni][0] + bx, acc[mi][ni][1] + by);
            *(float2*)&C[(size_t)(r + 8) * N + c] =
                make_float2(acc[mi][ni][2] + bx, acc[mi][ni][3] + by);
        }
    }
}

// ---------------- fused causal attention (single-pass, deferred normalize) --
#define SQH 0
#define SQL 18432
#define SKB 36864
#define SVB 110592
#define ASM 184320

__global__ __launch_bounds__(256) void k_attn(const bf16* __restrict__ qkvh,
                                              const bf16* __restrict__ qkvl,
                                              const bf16* __restrict__ vth,
                                              const bf16* __restrict__ vtl,
                                              float* __restrict__ wts,
                                              float* __restrict__ lg,
                                              bf16* __restrict__ atth,
                                              bf16* __restrict__ attl) {
    extern __shared__ char smem[];
    uint32_t sb = smem_u32(smem);

    const int tid = threadIdx.x, lane = tid & 31, wid = tid >> 5;
    const int i = 15 - blockIdx.x;            // heavy tiles first
    const int bh = blockIdx.y, b = bh >> 4, h = bh & 15;
    float* wbase = wts + ((size_t)bh * Tt + i * 128) * Tt;

    const bf16* qb_h = qkvh + ((size_t)b * Tt + i * 128) * D3 + h * 64;
    const bf16* qb_l = qkvl + ((size_t)b * Tt + i * 128) * D3 + h * 64;
    const bf16* kbase_h = qkvh + (size_t)b * Tt * D3 + Dd + h * 64;
    const bf16* kbase_l = qkvl + (size_t)b * Tt * D3 + Dd + h * 64;
    const bf16* vb_h = vth + (size_t)bh * 64 * Tt;
    const bf16* vb_l = vtl + (size_t)bh * 64 * Tt;

    const int wm = wid * 16;                  // warp's 16-row strip
    const int g = lane >> 2, qq = lane & 3;
    const int r0 = wm + g;                    // local row (and r0+8)

    // Q (group), K0 (group), V0 (group)
    cpa_tile(sb + SQH, qb_h, D3, 128);
    cpa_tile(sb + SQL, qb_l, D3, 128);
    CPCOMMIT();
    cpa_tile(sb + SKB,         kbase_h, D3, 128);
    cpa_tile(sb + SKB + 18432, kbase_l, D3, 128);
    CPCOMMIT();
    cpa_tile(sb + SVB,         vb_h,      Tt, 64);
    cpa_tile(sb + SVB + 9216,  vb_l,      Tt, 64);
    cpa_tile(sb + SVB + 18432, vb_h + 64, Tt, 64);
    cpa_tile(sb + SVB + 27648, vb_l + 64, Tt, 64);
    CPCOMMIT();

    float l0 = 0.f, l1 = 0.f;
    float accO[8][4];
    #pragma unroll
    for (int ni = 0; ni < 8; ni++)
        #pragma unroll
        for (int q = 0; q < 4; q++) accO[ni][q] = 0.f;

    // ---- single loop: S -> exp -> W + reg-P -> PV ----
    for (int kt = 0; kt <= i; kt++) {
        if (kt < i) {
            uint32_t stk = sb + SKB + ((kt + 1) & 1) * 36864;
            cpa_tile(stk,         kbase_h + (size_t)(kt + 1) * 128 * D3, D3, 128);
            cpa_tile(stk + 18432, kbase_l + (size_t)(kt + 1) * 128 * D3, D3, 128);
            CPCOMMIT();
            uint32_t stv = sb + SVB + ((kt + 1) & 1) * 36864;
            cpa_tile(stv,         vb_h + (kt + 1) * 128,      Tt, 64);
            cpa_tile(stv + 9216,  vb_l + (kt + 1) * 128,      Tt, 64);
            cpa_tile(stv + 18432, vb_h + (kt + 1) * 128 + 64, Tt, 64);
            cpa_tile(stv + 27648, vb_l + (kt + 1) * 128 + 64, Tt, 64);
            CPCOMMIT();
            CPWAIT2();                        // K_kt, V_kt (and older) ready
        } else CPWAIT0();
        __syncthreads();

        uint32_t stK = sb + SKB + (kt & 1) * 36864;
        uint32_t stV = sb + SVB + (kt & 1) * 36864;

        float accS[1][16][4];
        #pragma unroll
        for (int ni = 0; ni < 16; ni++)
            #pragma unroll
            for (int q = 0; q < 4; q++) accS[0][ni][q] = 0.f;
        mma_pass<1, 16, 4, 144>(accS, sb + SQH, stK,         lane, wm, 0);
        mma_pass<1, 16, 4, 144>(accS, sb + SQH, stK + 18432, lane, wm, 0);
        mma_pass<1, 16, 4, 144>(accS, sb + SQL, stK,         lane, wm, 0);

        // exp, unnormalized W write, register P fragments, l accumulation
        uint32_t phi[8][4], plo[8][4];
        #pragma unroll
        for (int ni = 0; ni < 16; ni++) {
            int c = ni * 8 + qq * 2;
            float v0 = accS[0][ni][0] * 0.125f, v1 = accS[0][ni][1] * 0.125f;
            float v2 = accS[0][ni][2] * 0.125f, v3 = accS[0][ni][3] * 0.125f;
            if (kt == i) {
                if (c     > r0)     v0 = -INFINITY;
                if (c + 1 > r0)     v1 = -INFINITY;
                if (c     > r0 + 8) v2 = -INFINITY;
                if (c + 1 > r0 + 8) v3 = -INFINITY;
            }
            float p0 = __expf(v0), p1 = __expf(v1);
            float p2 = __expf(v2), p3 = __expf(v3);
            l0 += p0 + p1;
            l1 += p2 + p3;
            *(float2*)&wbase[(size_t)r0 * Tt + kt * 128 + c] = make_float2(p0, p1);
            *(float2*)&wbase[(size_t)(r0 + 8) * Tt + kt * 128 + c] = make_float2(p2, p3);
            int kb = ni >> 1, hf = (ni & 1) << 1;
            split2r(p0, p1, phi[kb][hf],     plo[kb][hf]);
            split2r(p2, p3, phi[kb][hf + 1], plo[kb][hf + 1]);
        }

        #pragma unroll
        for (int cchunk = 0; cchunk < 2; cchunk++) {
            uint32_t svh = stV + cchunk * 18432;
            pv_pass(accO, phi + 4 * cchunk, svh,        lane);
            pv_pass(accO, phi + 4 * cchunk, svh + 9216, lane);
            pv_pass(accO, plo + 4 * cchunk, svh,        lane);
        }
        __syncthreads();   // protect stage reuse
    }

    // finish row sums within lane-quads, export l, normalize O
    l0 += __shfl_xor_sync(0xffffffffu, l0, 1);
    l0 += __shfl_xor_sync(0xffffffffu, l0, 2);
    l1 += __shfl_xor_sync(0xffffffffu, l1, 1);
    l1 += __shfl_xor_sync(0xffffffffu, l1, 2);
    if (qq == 0) {
        lg[(size_t)bh * Tt + i * 128 + r0]     = l0;
        lg[(size_t)bh * Tt + i * 128 + r0 + 8] = l1;
    }
    const float il0 = 1.f / l0, il1 = 1.f / l1;

    {
        int q0 = i * 128 + r0;
        size_t base0 = ((size_t)b * Tt + q0) * Dd + h * 64;
        size_t base8 = base0 + (size_t)8 * Dd;
        #pragma unroll
        for (int ni = 0; ni < 8; ni++) {
            int c = ni * 8 + qq * 2;
            st_split2(atth, attl, base0 + c, accO[ni][0] * il0, accO[ni][1] * il0);
            st_split2(atth, attl, base8 + c, accO[ni][2] * il1, accO[ni][3] * il1);
        }
    }
}

// zero the causal upper-triangle tail of W (independent of everything)
__global__ __launch_bounds__(256) void k_wzero(float* __restrict__ w) {
    const int row = blockIdx.x;               // 0 .. BHn*Tt-1
    const int r = row & (Tt - 1);
    const int tail0 = ((r >> 7) + 1) * 128;   // first zero column (tile-aligned)
    const int n4 = (Tt - tail0) >> 2;
    if (n4 <= 0) return;
    float4* p = (float4*)(w + (size_t)row * Tt + tail0);
    const float4 z = make_float4(0.f, 0.f, 0.f, 0.f);
    for (int e = threadIdx.x; e < n4; e += 256) p[e] = z;
}

// streaming W normalization: row *= 1/l over the causal tile prefix
__global__ __launch_bounds__(128) void k_wscale(float* __restrict__ w,
                                                const float* __restrict__ lg) {
    const int row = blockIdx.x;
    const float il = 1.f / lg[row];
    const int r = row & (Tt - 1);
    const int n4 = ((r >> 7) + 1) * 32;       // float4 count (tile-aligned prefix)
    float4* p = (float4*)(w + (size_t)row * Tt);
    for (int e = threadIdx.x; e < n4; e += 128) {
        float4 v = p[e];
        v.x *= il; v.y *= il; v.z *= il; v.w *= il;
        p[e] = v;
    }
}

// ---------------- prepasses ----------------
__global__ __launch_bounds__(256) void k_conv_x(const float* __restrict__ X,
                                                bf16* __restrict__ hi, bf16* __restrict__ lo,
                                                int n4) {
    int idx = blockIdx.x * 256 + threadIdx.x;
    if (idx >= n4) return;
    float4 v = ((const float4*)X)[idx];
    bf16 h0 = __float2bfloat16(v.x), h1 = __float2bfloat16(v.y);
    bf16 h2 = __float2bfloat16(v.z), h3 = __float2bfloat16(v.w);
    ((uint64_t*)hi)[idx] = pack4(h0, h1, h2, h3);
    ((uint64_t*)lo)[idx] = pack4(__float2bfloat16(v.x - __bfloat162float(h0)),
                                 __float2bfloat16(v.y - __bfloat162float(h1)),
                                 __float2bfloat16(v.z - __bfloat162float(h2)),
                                 __float2bfloat16(v.w - __bfloat162float(h3)));
}

__global__ __launch_bounds__(256) void k_conv_w(const float* __restrict__ W,
                                                bf16* __restrict__ hi, bf16* __restrict__ lo,
                                                int K, int N) {
    __shared__ float tile[32][33];
    const int n0 = blockIdx.x * 32, k0 = blockIdx.y * 32;
    const int tx = threadIdx.x & 31, ty = threadIdx.x >> 5;
    for (int r = ty; r < 32; r += 8) tile[r][tx] = W[(size_t)(k0 + r) * N + n0 + tx];
    __syncthreads();
    for (int r = ty; r < 32; r += 8) {
        float v = tile[tx][r];
        size_t o = (size_t)(n0 + r) * K + k0 + tx;
        bf16 h = __float2bfloat16(v);
        hi[o] = h;
        lo[o] = __float2bfloat16(v - __bfloat162float(h));
    }
}

__global__ __launch_bounds__(256) void k_conv_vt(const bf16* __restrict__ qh,
                                                 const bf16* __restrict__ ql,
                                                 bf16* __restrict__ hi, bf16* __restrict__ lo) {
    __shared__ bf16 th[32][33], tl[32][33];
    const int bh = blockIdx.z, b = bh >> 4, h = bh & 15;
    const int t0 = blockIdx.x * 32, d0 = blockIdx.y * 32;
    const int tx = threadIdx.x & 31, ty = threadIdx.x >> 5;
    const size_t sbase = ((size_t)b * Tt + t0) * D3 + 2 * Dd + h * 64 + d0;
    for (int r = ty; r < 32; r += 8) {
        th[r][tx] = qh[sbase + (size_t)r * D3 + tx];
        tl[r][tx] = ql[sbase + (size_t)r * D3 + tx];
    }
    __syncthreads();
    bf16* oh = hi + (size_t)bh * 64 * Tt;
    bf16* ol = lo + (size_t)bh * 64 * Tt;
    for (int r = ty; r < 32; r += 8) {
        size_t o = (size_t)(d0 + r) * Tt + t0 + tx;
        oh[o] = th[tx][r];
        ol[o] = tl[tx][r];
    }
}

// ---------------------------------------------------------------------------
extern "C" void kernel_launch(void* const* d_in, const int* in_sizes, int n_in,
                              void* d_out, int out_size) {
    const float* x    = (const float*)d_in[0];
    const float* Wqkv = (const float*)d_in[2];
    const float* Wo   = (const float*)d_in[3];
    const float* bo   = (const float*)d_in[4];

    float* out = (float*)d_out;                 // [B,T,D]
    float* wts = out + (size_t)NT * Dd;         // [B,H,T,T]

    bf16 *qkvh, *qkvl, *xh, *xl, *atth, *attl;
    bf16 *wth, *wtl, *woth, *wotl, *vth, *vtl;
    float* lg;
    cudaGetSymbolAddress((void**)&qkvh, g_qkv_hi);
    cudaGetSymbolAddress((void**)&qkvl, g_qkv_lo);
    cudaGetSymbolAddress((void**)&xh,   g_x_hi);
    cudaGetSymbolAddress((void**)&xl,   g_x_lo);
    cudaGetSymbolAddress((void**)&atth, g_att_hi);
    cudaGetSymbolAddress((void**)&attl, g_att_lo);
    cudaGetSymbolAddress((void**)&wth,  g_wt_hi);
    cudaGetSymbolAddress((void**)&wtl,  g_wt_lo);
    cudaGetSymbolAddress((void**)&woth, g_wot_hi);
    cudaGetSymbolAddress((void**)&wotl, g_wot_lo);
    cudaGetSymbolAddress((void**)&vth,  g_vt_hi);
    cudaGetSymbolAddress((void**)&vtl,  g_vt_lo);
    cudaGetSymbolAddress((void**)&lg,   g_l);

    cudaFuncSetAttribute(k_gemm_bf,  cudaFuncAttributeMaxDynamicSharedMemorySize, GSM);
    cudaFuncSetAttribute(k_gemm_f32, cudaFuncAttributeMaxDynamicSharedMemorySize, GSM);
    cudaFuncSetAttribute(k_attn,     cudaFuncAttributeMaxDynamicSharedMemorySize, ASM);

    cudaStream_t s2;
    cudaEvent_t e0, e1, e_fork, e_join;
    bool forked = (cudaStreamCreateWithFlags(&s2, cudaStreamNonBlocking) == cudaSuccess) &&
                  (cudaEventCreateWithFlags(&e0, cudaEventDisableTiming) == cudaSuccess) &&
                  (cudaEventCreateWithFlags(&e1, cudaEventDisableTiming) == cudaSuccess) &&
                  (cudaEventCreateWithFlags(&e_fork, cudaEventDisableTiming) == cudaSuccess) &&
                  (cudaEventCreateWithFlags(&e_join, cudaEventDisableTiming) == cudaSuccess);

    // 0) W causal-tail zeroing overlaps the whole pre-attention window
    if (forked) {
        cudaEventRecord(e0, 0);
        cudaStreamWaitEvent(s2, e0, 0);
        k_wzero<<<BHn * Tt, 256, 0, s2>>>(wts);
        cudaEventRecord(e1, s2);
    }

    // prepasses
    k_conv_w<<<dim3(D3 / 32, Dd / 32), 256>>>(Wqkv, wth, wtl, Dd, D3);
    k_conv_w<<<dim3(Dd / 32, Dd / 32), 256>>>(Wo, woth, wotl, Dd, Dd);
    k_conv_x<<<(NT * Dd / 4 + 255) / 256, 256>>>(x, xh, xl, NT * Dd / 4);

    // 1) QKV projection -> hi/lo bf16
    k_gemm_bf<<<dim3(D3 / 128, NT / 128), 256, GSM>>>(xh, xl, wth, wtl, qkvh, qkvl, Dd, D3);

    // 2) V transpose
    k_conv_vt<<<dim3(Tt / 32, 2, BHn), 256>>>(qkvh, qkvl, vth, vtl);

    if (!forked) k_wzero<<<BHn * Tt, 256>>>(wts);
    else cudaStreamWaitEvent(0, e1, 0);           // join zeroing before attn

    // 3) fused attention (single pass; W unnormalized, l exported)
    k_attn<<<dim3(16, BHn), 256, ASM>>>(qkvh, qkvl, vth, vtl, wts, lg, atth, attl);

    // 4) + 5) O-projection and W-normalization on parallel branches
    if (forked) {
        cudaEventRecord(e_fork, 0);
        cudaStreamWaitEvent(s2, e_fork, 0);
        k_wscale<<<BHn * Tt, 128, 0, s2>>>(wts, lg);
        cudaEventRecord(e_join, s2);
        k_gemm_f32<<<dim3(Dd / 128, NT / 128), 256, GSM>>>(atth, attl, woth, wotl, bo, out, Dd, Dd);
        cudaStreamWaitEvent(0, e_join, 0);
    } else {
        k_gemm_f32<<<dim3(Dd / 128, NT / 128), 256, GSM>>>(atth, attl, woth, wotl, bo, out, Dd, Dd);
        k_wscale<<<BHn * Tt, 128>>>(wts, lg);
    }
}